// round 1
// baseline (speedup 1.0000x reference)
#include <cuda_runtime.h>
#include <math.h>

// Problem constants
#define B_    4
#define N_    4096
#define M_    1024
#define QD_   1024
#define CD_   768
#define H_    8
#define DH_   64
#define INNER_ 512
#define SCALE_ 0.125f

// Scratch (no allocation allowed -> __device__ globals)
__device__ float g_Q[(size_t)B_ * N_ * INNER_];   // [B,N,INNER]
__device__ float g_K[(size_t)B_ * M_ * INNER_];   // [B,M,INNER]
__device__ float g_V[(size_t)B_ * M_ * INNER_];   // [B,M,INNER]
__device__ float g_O[(size_t)B_ * N_ * INNER_];   // attention output [B,N,INNER]

// ---------------------------------------------------------------------------
// Tiled SGEMM: C[M,N] = A[M,K] @ B[K,N] (+ bias[N] if bias != nullptr)
// BM=BN=128, BK=8, 256 threads, 8x8 per-thread microtile.
// Requires M%128==0, N%128==0, K%8==0 (true for all call sites).
// ---------------------------------------------------------------------------
__global__ __launch_bounds__(256) void sgemm128(
    const float* __restrict__ A, const float* __restrict__ Bm,
    float* __restrict__ C, const float* __restrict__ bias,
    int M, int N, int K)
{
    __shared__ float As[8][128];   // transposed: As[k][m]
    __shared__ float Bs[8][128];   // Bs[k][n]

    const int tid  = threadIdx.x;
    const int row0 = blockIdx.y * 128;
    const int col0 = blockIdx.x * 128;
    const int tx   = tid & 15;     // 16 col groups
    const int ty   = tid >> 4;     // 16 row groups

    const int aRow = tid >> 1;         // 0..127
    const int aCol = (tid & 1) * 4;    // 0 or 4
    const int bRow = tid >> 5;         // 0..7
    const int bCol = (tid & 31) * 4;   // 0..124

    const float* Ap = A + (size_t)(row0 + aRow) * K + aCol;
    const float* Bp = Bm + (size_t)bRow * N + col0 + bCol;

    float acc[8][8];
#pragma unroll
    for (int i = 0; i < 8; i++)
#pragma unroll
        for (int j = 0; j < 8; j++) acc[i][j] = 0.f;

    const int ntiles = K >> 3;
    for (int kt = 0; kt < ntiles; kt++) {
        float4 av = *(const float4*)Ap;  Ap += 8;
        float4 bv = *(const float4*)Bp;  Bp += (size_t)8 * N;

        __syncthreads();   // previous iteration finished reading smem
        As[aCol + 0][aRow] = av.x;
        As[aCol + 1][aRow] = av.y;
        As[aCol + 2][aRow] = av.z;
        As[aCol + 3][aRow] = av.w;
        *(float4*)&Bs[bRow][bCol] = bv;
        __syncthreads();

#pragma unroll
        for (int kk = 0; kk < 8; kk++) {
            float a[8], b[8];
#pragma unroll
            for (int i = 0; i < 8; i++) a[i] = As[kk][ty * 8 + i];
#pragma unroll
            for (int j = 0; j < 8; j++) b[j] = Bs[kk][tx * 8 + j];
#pragma unroll
            for (int i = 0; i < 8; i++)
#pragma unroll
                for (int j = 0; j < 8; j++)
                    acc[i][j] = fmaf(a[i], b[j], acc[i][j]);
        }
    }

    float bvals[8];
#pragma unroll
    for (int j = 0; j < 8; j++)
        bvals[j] = bias ? bias[col0 + tx * 8 + j] : 0.f;

#pragma unroll
    for (int i = 0; i < 8; i++) {
        float* crow = C + (size_t)(row0 + ty * 8 + i) * N + col0 + tx * 8;
        float4 v0 = make_float4(acc[i][0] + bvals[0], acc[i][1] + bvals[1],
                                acc[i][2] + bvals[2], acc[i][3] + bvals[3]);
        float4 v1 = make_float4(acc[i][4] + bvals[4], acc[i][5] + bvals[5],
                                acc[i][6] + bvals[6], acc[i][7] + bvals[7]);
        *(float4*)(crow)     = v0;
        *(float4*)(crow + 4) = v1;
    }
}

// ---------------------------------------------------------------------------
// Fused flash attention (fp32): per block = 64 queries of one (b,h).
// 128 threads: 2 threads per query row; thread p of a pair owns dims {p, p+2,...}
// (interleaved split -> conflict-free smem reads).
// Online softmax over KV tiles of 32.
// ---------------------------------------------------------------------------
__global__ __launch_bounds__(128) void attn_kernel(
    const float* __restrict__ Q, const float* __restrict__ K,
    const float* __restrict__ V, float* __restrict__ O)
{
    __shared__ float Qs[64][64];   // 16 KB
    __shared__ float Ks[32][64];   // 8 KB
    __shared__ float Vs[32][64];   // 8 KB

    const int b  = blockIdx.z;
    const int h  = blockIdx.y;
    const int q0 = blockIdx.x * 64;
    const int tid = threadIdx.x;
    const int r = tid >> 1;    // query row within tile (0..63)
    const int p = tid & 1;     // half (even/odd dims)

    // Load Q tile (coalesced in d)
    for (int i = tid; i < 64 * 64; i += 128) {
        int row = i >> 6, d = i & 63;
        Qs[row][d] = Q[((size_t)(b * N_ + q0 + row)) * INNER_ + h * DH_ + d];
    }
    __syncthreads();

    float q[32], acc[32];
#pragma unroll
    for (int i = 0; i < 32; i++) { q[i] = Qs[r][2 * i + p]; acc[i] = 0.f; }

    float mx = -1e30f, l = 0.f;

    for (int t = 0; t < M_ / 32; t++) {
        __syncthreads();   // previous tile's readers done
        for (int i = tid; i < 32 * 64; i += 128) {
            int row = i >> 6, d = i & 63;
            size_t gidx = ((size_t)(b * M_ + t * 32 + row)) * INNER_ + h * DH_ + d;
            Ks[row][d] = K[gidx];
            Vs[row][d] = V[gidx];
        }
        __syncthreads();

        // S = Q K^T for this row: each thread does half the dot, pair-combine.
        float s[32];
#pragma unroll
        for (int j = 0; j < 32; j++) {
            float a = 0.f;
#pragma unroll
            for (int i = 0; i < 32; i++)
                a = fmaf(q[i], Ks[j][2 * i + p], a);
            a += __shfl_xor_sync(0xffffffffu, a, 1);
            s[j] = a * SCALE_;
        }

        // Online softmax update
        float tmax = mx;
#pragma unroll
        for (int j = 0; j < 32; j++) tmax = fmaxf(tmax, s[j]);
        float corr = __expf(mx - tmax);
        mx = tmax;
        l *= corr;
#pragma unroll
        for (int i = 0; i < 32; i++) acc[i] *= corr;

#pragma unroll
        for (int j = 0; j < 32; j++) {
            float pj = __expf(s[j] - mx);
            l += pj;
#pragma unroll
            for (int i = 0; i < 32; i++)
                acc[i] = fmaf(pj, Vs[j][2 * i + p], acc[i]);
        }
    }

    const float inv = 1.f / l;
    const size_t o0 = ((size_t)(b * N_ + q0 + r)) * INNER_ + h * DH_ + p;
#pragma unroll
    for (int i = 0; i < 32; i++)
        O[o0 + 2 * i] = acc[i] * inv;
}

// ---------------------------------------------------------------------------
extern "C" void kernel_launch(void* const* d_in, const int* in_sizes, int n_in,
                              void* d_out, int out_size)
{
    const float* x   = (const float*)d_in[0];  // [4,4096,1024]
    const float* ctx = (const float*)d_in[1];  // [4,1024,768]
    const float* Wq  = (const float*)d_in[2];  // [1024,512]
    const float* Wk  = (const float*)d_in[3];  // [768,512]
    const float* Wv  = (const float*)d_in[4];  // [768,512]
    const float* Wo  = (const float*)d_in[5];  // [512,1024]
    const float* bo  = (const float*)d_in[6];  // [1024]
    float* out = (float*)d_out;                // [4,4096,1024]

    float *Qp, *Kp, *Vp, *Op;
    cudaGetSymbolAddress((void**)&Qp, g_Q);
    cudaGetSymbolAddress((void**)&Kp, g_K);
    cudaGetSymbolAddress((void**)&Vp, g_V);
    cudaGetSymbolAddress((void**)&Op, g_O);

    const dim3 blk(256);

    // Q = x @ Wq            : M=16384, N=512,  K=1024
    sgemm128<<<dim3(512 / 128, 16384 / 128), blk>>>(x, Wq, Qp, nullptr, 16384, 512, 1024);
    // K = context @ Wk      : M=4096,  N=512,  K=768
    sgemm128<<<dim3(512 / 128, 4096 / 128), blk>>>(ctx, Wk, Kp, nullptr, 4096, 512, 768);
    // V = context @ Wv
    sgemm128<<<dim3(512 / 128, 4096 / 128), blk>>>(ctx, Wv, Vp, nullptr, 4096, 512, 768);
    // Attention: O = softmax(QK^T * scale) V
    attn_kernel<<<dim3(N_ / 64, H_, B_), 128>>>(Qp, Kp, Vp, Op);
    // out = O @ Wo + bo     : M=16384, N=1024, K=512
    sgemm128<<<dim3(1024 / 128, 16384 / 128), blk>>>(Op, Wo, out, bo, 16384, 1024, 512);
}

// round 3
// speedup vs baseline: 4.1099x; 4.1099x over previous
#include <cuda_runtime.h>
#include <cstdint>
#include <math.h>

#define B_     4
#define N_     4096
#define M_     1024
#define QD_    1024
#define CD_    768
#define H_     8
#define DH_    64
#define INNER_ 512
#define SCALE_ 0.125f

// ---------------- scratch (__device__ globals; no allocation allowed) -------
__device__ float g_x  [(size_t)B_ * N_ * QD_];      // tf32-rounded x
__device__ float g_ctx[(size_t)B_ * M_ * CD_];      // tf32-rounded context
__device__ float g_WqT[(size_t)INNER_ * QD_];
__device__ float g_WkT[(size_t)INNER_ * CD_];
__device__ float g_WvT[(size_t)INNER_ * CD_];
__device__ float g_WoT[(size_t)QD_ * INNER_];
__device__ float g_Q  [(size_t)B_ * N_ * INNER_];
__device__ float g_K  [(size_t)B_ * M_ * INNER_];
__device__ float g_V  [(size_t)B_ * M_ * INNER_];
__device__ float g_Vt [(size_t)B_ * H_ * DH_ * M_];
__device__ float g_S  [(size_t)B_ * H_ * N_ * M_]; // 512MB logits/probs
__device__ float g_O  [(size_t)B_ * N_ * INNER_];

// ---------------- helpers ---------------------------------------------------
__device__ __forceinline__ uint32_t smem_u32(const void* p) {
    uint32_t a;
    asm("{ .reg .u64 t; cvta.to.shared.u64 t, %1; cvt.u32.u64 %0, t; }"
        : "=r"(a) : "l"(p));
    return a;
}
__device__ __forceinline__ float rna_tf32(float x) {
    float r; asm("cvt.rna.tf32.f32 %0, %1;" : "=f"(r) : "f"(x)); return r;
}
__device__ __forceinline__ void cp16(uint32_t dst, const void* src) {
    asm volatile("cp.async.cg.shared.global [%0], [%1], 16;"
                 :: "r"(dst), "l"(src) : "memory");
}
__device__ __forceinline__ void mma_tf32_16x8x8(
    float* c, const uint32_t* a, const uint32_t* b) {
    asm volatile(
        "mma.sync.aligned.m16n8k8.row.col.f32.tf32.tf32.f32 "
        "{%0,%1,%2,%3}, {%4,%5,%6,%7}, {%8,%9}, {%0,%1,%2,%3};"
        : "+f"(c[0]), "+f"(c[1]), "+f"(c[2]), "+f"(c[3])
        : "r"(a[0]), "r"(a[1]), "r"(a[2]), "r"(a[3]),
          "r"(b[0]), "r"(b[1]));
}

// ---------------------------------------------------------------------------
// tf32 mma.sync GEMM: C[M,N] = A[M,K] * Bt[N,K]^T  (+bias, optional tf32-round)
// CTA tile 128x64x32, 256 threads (4x2 warps of 32x32), cp.async double buffer.
// Requires M%128==0, N%64==0, K%32==0 (true for all call sites).
// ---------------------------------------------------------------------------
__global__ __launch_bounds__(256) void gemm_mma(
    const float* __restrict__ A, const float* __restrict__ Bt,
    float* __restrict__ C, const float* __restrict__ bias,
    int K, int lda, int ldb, int ldc,
    long long soA, long long siA, long long soB, long long siB,
    long long soC, long long siC, int Hdiv, int roundC)
{
    constexpr int BM = 128, BN = 64, BK = 32;
    constexpr int AST = BK + 4;                 // padded stride (words)
    constexpr int A_WORDS = BM * AST;           // 4608
    constexpr int STAGE_WORDS = (BM + BN) * AST; // 6912 (27648 B)

    extern __shared__ float sm[];
    const uint32_t sb = smem_u32(sm);

    const int tid = threadIdx.x, wid = tid >> 5, lane = tid & 31;
    const int gid = lane >> 2, tig = lane & 3;
    const int wm = (wid & 3) * 32, wn = (wid >> 2) * 32;

    const int z = blockIdx.z;
    const float* Ab = A + (long long)(z / Hdiv) * soA + (long long)(z % Hdiv) * siA;
    const float* Bb = Bt + (long long)(z / Hdiv) * soB + (long long)(z % Hdiv) * siB;
    float* Cb = C + (long long)(z / Hdiv) * soC + (long long)(z % Hdiv) * siC;
    const int row0 = blockIdx.y * BM;
    const int col0 = blockIdx.x * BN;

    // 6 fixed 16B chunks per thread per k-tile
    const float* ch_g[6];
    uint32_t ch_off[6];          // byte offset within a stage
    {
        int q = 0;
        for (int c = tid; c < (BM + BN) * 8; c += 256, q++) {
            if (c < BM * 8) {
                int r = c >> 3, h = c & 7;
                ch_g[q]   = Ab + (size_t)(row0 + r) * lda + h * 4;
                ch_off[q] = (uint32_t)(r * AST + h * 4) * 4u;
            } else {
                int cb = c - BM * 8, r = cb >> 3, h = cb & 7;
                ch_g[q]   = Bb + (size_t)(col0 + r) * ldb + h * 4;
                ch_off[q] = (uint32_t)(A_WORDS + r * AST + h * 4) * 4u;
            }
        }
    }

    float acc[2][4][4];
#pragma unroll
    for (int mi = 0; mi < 2; mi++)
#pragma unroll
        for (int ni = 0; ni < 4; ni++)
#pragma unroll
            for (int j = 0; j < 4; j++) acc[mi][ni][j] = 0.f;

    const int nt = K >> 5;

    // prefetch tile 0 into stage 0
#pragma unroll
    for (int q = 0; q < 6; q++) cp16(sb + ch_off[q], ch_g[q]);
    asm volatile("cp.async.commit_group;" ::: "memory");

    for (int kt = 0; kt < nt; kt++) {
        const int s = kt & 1;
        if (kt + 1 < nt) {
            const uint32_t nb = sb + (uint32_t)((s ^ 1) * STAGE_WORDS) * 4u;
#pragma unroll
            for (int q = 0; q < 6; q++)
                cp16(nb + ch_off[q], ch_g[q] + (size_t)(kt + 1) * 32);
            asm volatile("cp.async.commit_group;" ::: "memory");
            asm volatile("cp.async.wait_group 1;" ::: "memory");
        } else {
            asm volatile("cp.async.wait_group 0;" ::: "memory");
        }
        __syncthreads();

        const float* As = sm + s * STAGE_WORDS;
        const float* Bs = As + A_WORDS;
#pragma unroll
        for (int kq = 0; kq < 4; kq++) {
            const int k0 = kq * 8;
            uint32_t a[2][4], b[4][2];
#pragma unroll
            for (int mi = 0; mi < 2; mi++) {
                const float* ap = As + (wm + mi * 16 + gid) * AST + k0 + tig;
                a[mi][0] = __float_as_uint(ap[0]);
                a[mi][1] = __float_as_uint(ap[8 * AST]);
                a[mi][2] = __float_as_uint(ap[4]);
                a[mi][3] = __float_as_uint(ap[8 * AST + 4]);
            }
#pragma unroll
            for (int ni = 0; ni < 4; ni++) {
                const float* bp = Bs + (wn + ni * 8 + gid) * AST + k0 + tig;
                b[ni][0] = __float_as_uint(bp[0]);
                b[ni][1] = __float_as_uint(bp[4]);
            }
#pragma unroll
            for (int mi = 0; mi < 2; mi++)
#pragma unroll
                for (int ni = 0; ni < 4; ni++)
                    mma_tf32_16x8x8(acc[mi][ni], a[mi], b[ni]);
        }
        __syncthreads();
    }

    // epilogue
#pragma unroll
    for (int mi = 0; mi < 2; mi++) {
#pragma unroll
        for (int half = 0; half < 2; half++) {
            const int m = row0 + wm + mi * 16 + gid + half * 8;
            float* crow = Cb + (size_t)m * ldc + col0 + wn;
#pragma unroll
            for (int ni = 0; ni < 4; ni++) {
                const int cc = ni * 8 + 2 * tig;
                float2 v;
                v.x = acc[mi][ni][half * 2 + 0];
                v.y = acc[mi][ni][half * 2 + 1];
                if (bias) {
                    v.x += bias[col0 + wn + cc + 0];
                    v.y += bias[col0 + wn + cc + 1];
                }
                if (roundC) { v.x = rna_tf32(v.x); v.y = rna_tf32(v.y); }
                *(float2*)(crow + cc) = v;
            }
        }
    }
}

// ---------------------------------------------------------------------------
// batched transpose with tf32 rounding: out[z][c][r] = rna(in[batch(z)][r][c])
// ---------------------------------------------------------------------------
__global__ void transpose_k(const float* __restrict__ in, float* __restrict__ out,
                            int rows, int cols, int ldin, int ldout,
                            long long soIn, long long siIn, long long soOut, int Hdiv)
{
    __shared__ float t[32][33];
    const int z = blockIdx.z;
    const float* ib = in + (long long)(z / Hdiv) * soIn + (long long)(z % Hdiv) * siIn;
    float* ob = out + (long long)z * soOut;
    const int c0 = blockIdx.x * 32, r0 = blockIdx.y * 32;
    const int x = threadIdx.x, y = threadIdx.y;
    for (int i = y; i < 32; i += 8) {
        int r = r0 + i, c = c0 + x;
        t[i][x] = (r < rows && c < cols) ? ib[(size_t)r * ldin + c] : 0.f;
    }
    __syncthreads();
    for (int i = y; i < 32; i += 8) {
        int orow = c0 + i, oc = r0 + x;
        if (orow < cols && oc < rows)
            ob[(size_t)orow * ldout + oc] = rna_tf32(t[x][i]);
    }
}

// elementwise tf32 rounding
__global__ void cvt_k(const float* __restrict__ in, float* __restrict__ out, int n4)
{
    int i = blockIdx.x * 256 + threadIdx.x;
    if (i < n4) {
        float4 v = ((const float4*)in)[i];
        v.x = rna_tf32(v.x); v.y = rna_tf32(v.y);
        v.z = rna_tf32(v.z); v.w = rna_tf32(v.w);
        ((float4*)out)[i] = v;
    }
}

// softmax over rows of 1024 with scale; output tf32-rounded (feeds PV MMA)
__global__ __launch_bounds__(256) void softmax_k(float* __restrict__ S)
{
    const int warp = threadIdx.x >> 5, lane = threadIdx.x & 31;
    const size_t row = (size_t)blockIdx.x * 8 + warp;
    float4* p = (float4*)(S + row * 1024);
    float4 v[8];
    float mx = -1e30f;
#pragma unroll
    for (int i = 0; i < 8; i++) {
        float4 t = p[lane + i * 32];
        t.x *= SCALE_; t.y *= SCALE_; t.z *= SCALE_; t.w *= SCALE_;
        v[i] = t;
        mx = fmaxf(mx, fmaxf(fmaxf(t.x, t.y), fmaxf(t.z, t.w)));
    }
#pragma unroll
    for (int o = 16; o; o >>= 1) mx = fmaxf(mx, __shfl_xor_sync(~0u, mx, o));
    float s = 0.f;
#pragma unroll
    for (int i = 0; i < 8; i++) {
        v[i].x = __expf(v[i].x - mx); v[i].y = __expf(v[i].y - mx);
        v[i].z = __expf(v[i].z - mx); v[i].w = __expf(v[i].w - mx);
        s += v[i].x + v[i].y + v[i].z + v[i].w;
    }
#pragma unroll
    for (int o = 16; o; o >>= 1) s += __shfl_xor_sync(~0u, s, o);
    const float inv = 1.f / s;
#pragma unroll
    for (int i = 0; i < 8; i++) {
        v[i].x = rna_tf32(v[i].x * inv); v[i].y = rna_tf32(v[i].y * inv);
        v[i].z = rna_tf32(v[i].z * inv); v[i].w = rna_tf32(v[i].w * inv);
        p[lane + i * 32] = v[i];
    }
}

// ---------------------------------------------------------------------------
extern "C" void kernel_launch(void* const* d_in, const int* in_sizes, int n_in,
                              void* d_out, int out_size)
{
    const float* x   = (const float*)d_in[0];
    const float* ctx = (const float*)d_in[1];
    const float* Wq  = (const float*)d_in[2];
    const float* Wk  = (const float*)d_in[3];
    const float* Wv  = (const float*)d_in[4];
    const float* Wo  = (const float*)d_in[5];
    const float* bo  = (const float*)d_in[6];
    float* out = (float*)d_out;

    float *xr, *cr, *WqT, *WkT, *WvT, *WoT, *Q, *Kp, *V, *Vt, *S, *O;
    cudaGetSymbolAddress((void**)&xr,  g_x);
    cudaGetSymbolAddress((void**)&cr,  g_ctx);
    cudaGetSymbolAddress((void**)&WqT, g_WqT);
    cudaGetSymbolAddress((void**)&WkT, g_WkT);
    cudaGetSymbolAddress((void**)&WvT, g_WvT);
    cudaGetSymbolAddress((void**)&WoT, g_WoT);
    cudaGetSymbolAddress((void**)&Q,   g_Q);
    cudaGetSymbolAddress((void**)&Kp,  g_K);
    cudaGetSymbolAddress((void**)&V,   g_V);
    cudaGetSymbolAddress((void**)&Vt,  g_Vt);
    cudaGetSymbolAddress((void**)&S,   g_S);
    cudaGetSymbolAddress((void**)&O,   g_O);

    const int SMEM = 2 * (128 + 64) * 36 * 4;   // 55296 bytes
    cudaFuncSetAttribute(gemm_mma, cudaFuncAttributeMaxDynamicSharedMemorySize, SMEM);

    const dim3 tb(256);

    // 0) tf32-round inputs
    cvt_k<<<16384, 256>>>(x, xr, (int)((size_t)B_ * N_ * QD_ / 4));
    cvt_k<<<3072, 256>>>(ctx, cr, (int)((size_t)B_ * M_ * CD_ / 4));

    // 1) weight transposes (rounded)
    dim3 t32(32, 8);
    transpose_k<<<dim3(16, 32, 1), t32>>>(Wq, WqT, 1024, 512, 512, 1024, 0, 0, 0, 1);
    transpose_k<<<dim3(16, 24, 1), t32>>>(Wk, WkT,  768, 512, 512,  768, 0, 0, 0, 1);
    transpose_k<<<dim3(16, 24, 1), t32>>>(Wv, WvT,  768, 512, 512,  768, 0, 0, 0, 1);
    transpose_k<<<dim3(32, 16, 1), t32>>>(Wo, WoT,  512, 1024, 1024, 512, 0, 0, 0, 1);

    // 2) projections (outputs tf32-rounded: they feed MMAs)
    gemm_mma<<<dim3(8, 128, 1), tb, SMEM>>>(xr, WqT, Q, nullptr,
        1024, 1024, 1024, 512, 0, 0, 0, 0, 0, 0, 1, 1);
    gemm_mma<<<dim3(8, 32, 1), tb, SMEM>>>(cr, WkT, Kp, nullptr,
        768, 768, 768, 512, 0, 0, 0, 0, 0, 0, 1, 1);
    gemm_mma<<<dim3(8, 32, 1), tb, SMEM>>>(cr, WvT, V, nullptr,
        768, 768, 768, 512, 0, 0, 0, 0, 0, 0, 1, 1);

    // 3) V -> Vt [bh][64][1024] (rounded)
    transpose_k<<<dim3(2, 32, 32), t32>>>(V, Vt, 1024, 64, 512, 1024,
        (long long)M_ * INNER_, 64, (long long)DH_ * M_, H_);

    // 4) S = Q K^T  (batched over b*h)
    gemm_mma<<<dim3(16, 32, 32), tb, SMEM>>>(Q, Kp, S, nullptr,
        64, 512, 512, 1024,
        (long long)N_ * INNER_, 64,
        (long long)M_ * INNER_, 64,
        (long long)H_ * N_ * M_, (long long)N_ * M_, H_, 0);

    // 5) softmax rows (scale + rounded probs)
    softmax_k<<<16384, 256>>>(S);

    // 6) O = P V  (batched)
    gemm_mma<<<dim3(1, 32, 32), tb, SMEM>>>(S, Vt, O, nullptr,
        1024, 1024, 1024, 512,
        (long long)H_ * N_ * M_, (long long)N_ * M_,
        (long long)H_ * DH_ * M_, (long long)DH_ * M_,
        (long long)N_ * INNER_, 64, H_, 1);

    // 7) out = O Wo + bo (full fp32 output)
    gemm_mma<<<dim3(16, 128, 1), tb, SMEM>>>(O, WoT, out, bo,
        512, 512, 512, 1024, 0, 0, 0, 0, 0, 0, 1, 0);
}

// round 4
// speedup vs baseline: 5.2822x; 1.2852x over previous
#include <cuda_runtime.h>
#include <cstdint>
#include <math.h>

#define B_     4
#define N_     4096
#define M_     1024
#define QD_    1024
#define CD_    768
#define H_     8
#define DH_    64
#define INNER_ 512
#define SCALE_ 0.125f

// ---------------- scratch (__device__ globals; no allocation allowed) -------
__device__ float g_x  [(size_t)B_ * N_ * QD_];      // tf32-rounded x
__device__ float g_ctx[(size_t)B_ * M_ * CD_];      // tf32-rounded context
__device__ float g_WqT[(size_t)INNER_ * QD_];
__device__ float g_WkT[(size_t)INNER_ * CD_];
__device__ float g_WvT[(size_t)INNER_ * CD_];
__device__ float g_WoT[(size_t)QD_ * INNER_];
__device__ float g_Q  [(size_t)B_ * N_ * INNER_];
__device__ float g_K  [(size_t)B_ * M_ * INNER_];
__device__ float g_V  [(size_t)B_ * M_ * INNER_];
__device__ float g_O  [(size_t)B_ * N_ * INNER_];

// ---------------- helpers ---------------------------------------------------
__device__ __forceinline__ uint32_t smem_u32(const void* p) {
    uint32_t a;
    asm("{ .reg .u64 t; cvta.to.shared.u64 t, %1; cvt.u32.u64 %0, t; }"
        : "=r"(a) : "l"(p));
    return a;
}
__device__ __forceinline__ float rna_tf32(float x) {
    float r; asm("cvt.rna.tf32.f32 %0, %1;" : "=f"(r) : "f"(x)); return r;
}
__device__ __forceinline__ void cp16(uint32_t dst, const void* src) {
    asm volatile("cp.async.cg.shared.global [%0], [%1], 16;"
                 :: "r"(dst), "l"(src) : "memory");
}
__device__ __forceinline__ void mma_tf32_16x8x8(
    float* c, const uint32_t* a, const uint32_t* b) {
    asm volatile(
        "mma.sync.aligned.m16n8k8.row.col.f32.tf32.tf32.f32 "
        "{%0,%1,%2,%3}, {%4,%5,%6,%7}, {%8,%9}, {%0,%1,%2,%3};"
        : "+f"(c[0]), "+f"(c[1]), "+f"(c[2]), "+f"(c[3])
        : "r"(a[0]), "r"(a[1]), "r"(a[2]), "r"(a[3]),
          "r"(b[0]), "r"(b[1]));
}

// ---------------------------------------------------------------------------
// tf32 mma.sync GEMM: C[M,N] = A[M,K] * Bt[N,K]^T  (+bias, optional tf32-round)
// CTA tile 128x64x32, 256 threads (4x2 warps of 32x32), cp.async double buffer.
// ---------------------------------------------------------------------------
__global__ __launch_bounds__(256) void gemm_mma(
    const float* __restrict__ A, const float* __restrict__ Bt,
    float* __restrict__ C, const float* __restrict__ bias,
    int K, int lda, int ldb, int ldc,
    long long soA, long long siA, long long soB, long long siB,
    long long soC, long long siC, int Hdiv, int roundC)
{
    constexpr int BM = 128, BN = 64, BK = 32;
    constexpr int AST = BK + 4;
    constexpr int A_WORDS = BM * AST;
    constexpr int STAGE_WORDS = (BM + BN) * AST;

    extern __shared__ float sm[];
    const uint32_t sb = smem_u32(sm);

    const int tid = threadIdx.x, wid = tid >> 5, lane = tid & 31;
    const int gid = lane >> 2, tig = lane & 3;
    const int wm = (wid & 3) * 32, wn = (wid >> 2) * 32;

    const int z = blockIdx.z;
    const float* Ab = A + (long long)(z / Hdiv) * soA + (long long)(z % Hdiv) * siA;
    const float* Bb = Bt + (long long)(z / Hdiv) * soB + (long long)(z % Hdiv) * siB;
    float* Cb = C + (long long)(z / Hdiv) * soC + (long long)(z % Hdiv) * siC;
    const int row0 = blockIdx.y * BM;
    const int col0 = blockIdx.x * BN;

    const float* ch_g[6];
    uint32_t ch_off[6];
    {
        int q = 0;
        for (int c = tid; c < (BM + BN) * 8; c += 256, q++) {
            if (c < BM * 8) {
                int r = c >> 3, h = c & 7;
                ch_g[q]   = Ab + (size_t)(row0 + r) * lda + h * 4;
                ch_off[q] = (uint32_t)(r * AST + h * 4) * 4u;
            } else {
                int cb = c - BM * 8, r = cb >> 3, h = cb & 7;
                ch_g[q]   = Bb + (size_t)(col0 + r) * ldb + h * 4;
                ch_off[q] = (uint32_t)(A_WORDS + r * AST + h * 4) * 4u;
            }
        }
    }

    float acc[2][4][4];
#pragma unroll
    for (int mi = 0; mi < 2; mi++)
#pragma unroll
        for (int ni = 0; ni < 4; ni++)
#pragma unroll
            for (int j = 0; j < 4; j++) acc[mi][ni][j] = 0.f;

    const int nt = K >> 5;
#pragma unroll
    for (int q = 0; q < 6; q++) cp16(sb + ch_off[q], ch_g[q]);
    asm volatile("cp.async.commit_group;" ::: "memory");

    for (int kt = 0; kt < nt; kt++) {
        const int s = kt & 1;
        if (kt + 1 < nt) {
            const uint32_t nb = sb + (uint32_t)((s ^ 1) * STAGE_WORDS) * 4u;
#pragma unroll
            for (int q = 0; q < 6; q++)
                cp16(nb + ch_off[q], ch_g[q] + (size_t)(kt + 1) * 32);
            asm volatile("cp.async.commit_group;" ::: "memory");
            asm volatile("cp.async.wait_group 1;" ::: "memory");
        } else {
            asm volatile("cp.async.wait_group 0;" ::: "memory");
        }
        __syncthreads();

        const float* As = sm + s * STAGE_WORDS;
        const float* Bs = As + A_WORDS;
#pragma unroll
        for (int kq = 0; kq < 4; kq++) {
            const int k0 = kq * 8;
            uint32_t a[2][4], b[4][2];
#pragma unroll
            for (int mi = 0; mi < 2; mi++) {
                const float* ap = As + (wm + mi * 16 + gid) * AST + k0 + tig;
                a[mi][0] = __float_as_uint(ap[0]);
                a[mi][1] = __float_as_uint(ap[8 * AST]);
                a[mi][2] = __float_as_uint(ap[4]);
                a[mi][3] = __float_as_uint(ap[8 * AST + 4]);
            }
#pragma unroll
            for (int ni = 0; ni < 4; ni++) {
                const float* bp = Bs + (wn + ni * 8 + gid) * AST + k0 + tig;
                b[ni][0] = __float_as_uint(bp[0]);
                b[ni][1] = __float_as_uint(bp[4]);
            }
#pragma unroll
            for (int mi = 0; mi < 2; mi++)
#pragma unroll
                for (int ni = 0; ni < 4; ni++)
                    mma_tf32_16x8x8(acc[mi][ni], a[mi], b[ni]);
        }
        __syncthreads();
    }

#pragma unroll
    for (int mi = 0; mi < 2; mi++) {
#pragma unroll
        for (int half = 0; half < 2; half++) {
            const int m = row0 + wm + mi * 16 + gid + half * 8;
            float* crow = Cb + (size_t)m * ldc + col0 + wn;
#pragma unroll
            for (int ni = 0; ni < 4; ni++) {
                const int cc = ni * 8 + 2 * tig;
                float2 v;
                v.x = acc[mi][ni][half * 2 + 0];
                v.y = acc[mi][ni][half * 2 + 1];
                if (bias) {
                    v.x += bias[col0 + wn + cc + 0];
                    v.y += bias[col0 + wn + cc + 1];
                }
                if (roundC) { v.x = rna_tf32(v.x); v.y = rna_tf32(v.y); }
                *(float2*)(crow + cc) = v;
            }
        }
    }
}

// ---------------------------------------------------------------------------
// Fused flash attention, tf32 mma.sync. CTA: 128 queries of one (b,h).
// 8 warps x 16 rows. KV tiles of 64, cp.async double-buffered. Online softmax.
// Q tile staged once -> register fragments; Q smem region reused as P staging.
// ---------------------------------------------------------------------------
__global__ __launch_bounds__(256, 2) void flash_k(
    const float* __restrict__ Q, const float* __restrict__ K,
    const float* __restrict__ V, float* __restrict__ O)
{
    constexpr int PAD = 68;
    constexpr int KV_WORDS = 64 * PAD;             // one K or V stage
    extern __shared__ float sm[];
    const uint32_t sb = smem_u32(sm);

    const int tid = threadIdx.x, wid = tid >> 5, lane = tid & 31;
    const int gid = lane >> 2, tig = lane & 3;
    const int b = blockIdx.z, h = blockIdx.y, q0 = blockIdx.x * 128;
    const int wrow = wid * 16;

    const float* Qg = Q + ((size_t)(b * N_ + q0)) * INNER_ + h * DH_;
    const float* Kg = K + ((size_t)b * M_) * INNER_ + h * DH_;
    const float* Vg = V + ((size_t)b * M_) * INNER_ + h * DH_;
    float*       Og = O + ((size_t)(b * N_ + q0)) * INNER_ + h * DH_;

    float* Ksm = sm;                      // [2][64][PAD]
    float* Vsm = sm + 2 * KV_WORDS;       // [2][64][PAD]
    float* QP  = sm + 4 * KV_WORDS;       // [128][PAD]  (Q stage, then P)

    const int lr = tid >> 4, lch = tid & 15;   // loader row-in-16 / chunk

    // ---- stage Q tile (coalesced) ----
#pragma unroll
    for (int i = 0; i < 8; i++) {
        const int row = i * 16 + lr;
        cp16(sb + (uint32_t)((4 * KV_WORDS + row * PAD + lch * 4) * 4),
             Qg + (size_t)row * INNER_ + lch * 4);
    }
    asm volatile("cp.async.commit_group;" ::: "memory");
    asm volatile("cp.async.wait_group 0;" ::: "memory");
    __syncthreads();

    // ---- Q fragments to registers ----
    uint32_t aq[8][4];
#pragma unroll
    for (int kq = 0; kq < 8; kq++) {
        const float* qp = QP + (wrow + gid) * PAD + kq * 8 + tig;
        aq[kq][0] = __float_as_uint(qp[0]);
        aq[kq][1] = __float_as_uint(qp[8 * PAD]);
        aq[kq][2] = __float_as_uint(qp[4]);
        aq[kq][3] = __float_as_uint(qp[8 * PAD + 4]);
    }

    float oacc[8][4];
#pragma unroll
    for (int ni = 0; ni < 8; ni++)
#pragma unroll
        for (int j = 0; j < 4; j++) oacc[ni][j] = 0.f;
    float m0 = -1e30f, m1 = -1e30f, l0 = 0.f, l1 = 0.f;

    // ---- KV prefetch (tile t -> stage s) ----
    auto prefetch = [&](int t, int s) {
#pragma unroll
        for (int q = 0; q < 4; q++) {
            const int row = q * 16 + lr;
            const uint32_t so = (uint32_t)(((s * 64 + row) * PAD + lch * 4) * 4);
            const size_t go = (size_t)(t * 64 + row) * INNER_ + lch * 4;
            cp16(sb + so, Kg + go);
            cp16(sb + (uint32_t)(2 * KV_WORDS * 4) + so, Vg + go);
        }
        asm volatile("cp.async.commit_group;" ::: "memory");
    };
    prefetch(0, 0);

    for (int t = 0; t < M_ / 64; t++) {
        const int s = t & 1;
        if (t + 1 < M_ / 64) {
            prefetch(t + 1, s ^ 1);
            asm volatile("cp.async.wait_group 1;" ::: "memory");
        } else {
            asm volatile("cp.async.wait_group 0;" ::: "memory");
        }
        __syncthreads();

        const float* Ks = Ksm + s * KV_WORDS;
        const float* Vs = Vsm + s * KV_WORDS;

        // ---- S = Q K^T (16x64 per warp) ----
        float sacc[8][4];
#pragma unroll
        for (int ni = 0; ni < 8; ni++)
#pragma unroll
            for (int j = 0; j < 4; j++) sacc[ni][j] = 0.f;
#pragma unroll
        for (int kq = 0; kq < 8; kq++) {
#pragma unroll
            for (int ni = 0; ni < 8; ni++) {
                const float* kp = Ks + (ni * 8 + gid) * PAD + kq * 8 + tig;
                uint32_t bb[2] = { __float_as_uint(kp[0]), __float_as_uint(kp[4]) };
                mma_tf32_16x8x8(sacc[ni], aq[kq], bb);
            }
        }

        // ---- online softmax ----
        float r0m = -1e30f, r1m = -1e30f;
#pragma unroll
        for (int ni = 0; ni < 8; ni++) {
#pragma unroll
            for (int j = 0; j < 4; j++) sacc[ni][j] *= SCALE_;
            r0m = fmaxf(r0m, fmaxf(sacc[ni][0], sacc[ni][1]));
            r1m = fmaxf(r1m, fmaxf(sacc[ni][2], sacc[ni][3]));
        }
        r0m = fmaxf(r0m, __shfl_xor_sync(~0u, r0m, 1));
        r0m = fmaxf(r0m, __shfl_xor_sync(~0u, r0m, 2));
        r1m = fmaxf(r1m, __shfl_xor_sync(~0u, r1m, 1));
        r1m = fmaxf(r1m, __shfl_xor_sync(~0u, r1m, 2));
        const float nm0 = fmaxf(m0, r0m), nm1 = fmaxf(m1, r1m);
        const float c0 = __expf(m0 - nm0), c1 = __expf(m1 - nm1);
        float s0 = 0.f, s1 = 0.f;
        float* Pw = QP + wrow * PAD;
#pragma unroll
        for (int ni = 0; ni < 8; ni++) {
            const float p0 = __expf(sacc[ni][0] - nm0);
            const float p1 = __expf(sacc[ni][1] - nm0);
            const float p2 = __expf(sacc[ni][2] - nm1);
            const float p3 = __expf(sacc[ni][3] - nm1);
            s0 += p0 + p1; s1 += p2 + p3;
            float2 v0 = make_float2(rna_tf32(p0), rna_tf32(p1));
            float2 v1 = make_float2(rna_tf32(p2), rna_tf32(p3));
            *(float2*)(Pw + gid * PAD + ni * 8 + 2 * tig) = v0;
            *(float2*)(Pw + (gid + 8) * PAD + ni * 8 + 2 * tig) = v1;
        }
        s0 += __shfl_xor_sync(~0u, s0, 1); s0 += __shfl_xor_sync(~0u, s0, 2);
        s1 += __shfl_xor_sync(~0u, s1, 1); s1 += __shfl_xor_sync(~0u, s1, 2);
        l0 = l0 * c0 + s0; l1 = l1 * c1 + s1;
        m0 = nm0; m1 = nm1;
#pragma unroll
        for (int ni = 0; ni < 8; ni++) {
            oacc[ni][0] *= c0; oacc[ni][1] *= c0;
            oacc[ni][2] *= c1; oacc[ni][3] *= c1;
        }
        __syncwarp();

        // ---- O += P V ----
#pragma unroll
        for (int kq = 0; kq < 8; kq++) {
            const float* pp = Pw + gid * PAD + kq * 8 + tig;
            uint32_t ap[4] = {
                __float_as_uint(pp[0]), __float_as_uint(pp[8 * PAD]),
                __float_as_uint(pp[4]), __float_as_uint(pp[8 * PAD + 4]) };
#pragma unroll
            for (int ni = 0; ni < 8; ni++) {
                const float* vp = Vs + (kq * 8 + tig) * PAD + ni * 8 + gid;
                uint32_t bb[2] = { __float_as_uint(vp[0]),
                                   __float_as_uint(vp[4 * PAD]) };
                mma_tf32_16x8x8(oacc[ni], ap, bb);
            }
        }
        __syncwarp();
        __syncthreads();
    }

    // ---- normalize + write O (tf32-rounded: feeds out-proj MMA) ----
    const float inv0 = 1.f / l0, inv1 = 1.f / l1;
#pragma unroll
    for (int ni = 0; ni < 8; ni++) {
        const int cc = ni * 8 + 2 * tig;
        float2 v0 = make_float2(rna_tf32(oacc[ni][0] * inv0),
                                rna_tf32(oacc[ni][1] * inv0));
        float2 v1 = make_float2(rna_tf32(oacc[ni][2] * inv1),
                                rna_tf32(oacc[ni][3] * inv1));
        *(float2*)(Og + (size_t)(wrow + gid) * INNER_ + cc) = v0;
        *(float2*)(Og + (size_t)(wrow + gid + 8) * INNER_ + cc) = v1;
    }
}

// ---------------------------------------------------------------------------
__global__ void transpose_k(const float* __restrict__ in, float* __restrict__ out,
                            int rows, int cols, int ldin, int ldout)
{
    __shared__ float t[32][33];
    const int c0 = blockIdx.x * 32, r0 = blockIdx.y * 32;
    const int x = threadIdx.x, y = threadIdx.y;
    for (int i = y; i < 32; i += 8) {
        int r = r0 + i, c = c0 + x;
        t[i][x] = (r < rows && c < cols) ? in[(size_t)r * ldin + c] : 0.f;
    }
    __syncthreads();
    for (int i = y; i < 32; i += 8) {
        int orow = c0 + i, oc = r0 + x;
        if (orow < cols && oc < rows)
            out[(size_t)orow * ldout + oc] = rna_tf32(t[x][i]);
    }
}

__global__ void cvt_k(const float* __restrict__ in, float* __restrict__ out, int n4)
{
    int i = blockIdx.x * 256 + threadIdx.x;
    if (i < n4) {
        float4 v = ((const float4*)in)[i];
        v.x = rna_tf32(v.x); v.y = rna_tf32(v.y);
        v.z = rna_tf32(v.z); v.w = rna_tf32(v.w);
        ((float4*)out)[i] = v;
    }
}

// ---------------------------------------------------------------------------
extern "C" void kernel_launch(void* const* d_in, const int* in_sizes, int n_in,
                              void* d_out, int out_size)
{
    const float* x   = (const float*)d_in[0];
    const float* ctx = (const float*)d_in[1];
    const float* Wq  = (const float*)d_in[2];
    const float* Wk  = (const float*)d_in[3];
    const float* Wv  = (const float*)d_in[4];
    const float* Wo  = (const float*)d_in[5];
    const float* bo  = (const float*)d_in[6];
    float* out = (float*)d_out;

    float *xr, *cr, *WqT, *WkT, *WvT, *WoT, *Q, *Kp, *V, *O;
    cudaGetSymbolAddress((void**)&xr,  g_x);
    cudaGetSymbolAddress((void**)&cr,  g_ctx);
    cudaGetSymbolAddress((void**)&WqT, g_WqT);
    cudaGetSymbolAddress((void**)&WkT, g_WkT);
    cudaGetSymbolAddress((void**)&WvT, g_WvT);
    cudaGetSymbolAddress((void**)&WoT, g_WoT);
    cudaGetSymbolAddress((void**)&Q,   g_Q);
    cudaGetSymbolAddress((void**)&Kp,  g_K);
    cudaGetSymbolAddress((void**)&V,   g_V);
    cudaGetSymbolAddress((void**)&O,   g_O);

    const int SMEM_G = 2 * (128 + 64) * 36 * 4;            // 55296 B
    const int SMEM_F = (4 * 64 * 68 + 128 * 68) * 4;       // 104448 B
    cudaFuncSetAttribute(gemm_mma, cudaFuncAttributeMaxDynamicSharedMemorySize, SMEM_G);
    cudaFuncSetAttribute(flash_k,  cudaFuncAttributeMaxDynamicSharedMemorySize, SMEM_F);

    const dim3 tb(256);
    dim3 t32(32, 8);

    // 0) tf32-round inputs
    cvt_k<<<16384, 256>>>(x, xr, (int)((size_t)B_ * N_ * QD_ / 4));
    cvt_k<<<3072, 256>>>(ctx, cr, (int)((size_t)B_ * M_ * CD_ / 4));

    // 1) weight transposes (rounded)
    transpose_k<<<dim3(16, 32), t32>>>(Wq, WqT, 1024, 512, 512, 1024);
    transpose_k<<<dim3(16, 24), t32>>>(Wk, WkT,  768, 512, 512,  768);
    transpose_k<<<dim3(16, 24), t32>>>(Wv, WvT,  768, 512, 512,  768);
    transpose_k<<<dim3(32, 16), t32>>>(Wo, WoT,  512, 1024, 1024, 512);

    // 2) projections (tf32-rounded outputs feed the flash MMAs)
    gemm_mma<<<dim3(8, 128, 1), tb, SMEM_G>>>(xr, WqT, Q, nullptr,
        1024, 1024, 1024, 512, 0, 0, 0, 0, 0, 0, 1, 1);
    gemm_mma<<<dim3(8, 32, 1), tb, SMEM_G>>>(cr, WkT, Kp, nullptr,
        768, 768, 768, 512, 0, 0, 0, 0, 0, 0, 1, 1);
    gemm_mma<<<dim3(8, 32, 1), tb, SMEM_G>>>(cr, WvT, V, nullptr,
        768, 768, 768, 512, 0, 0, 0, 0, 0, 0, 1, 1);

    // 3) fused flash attention -> O (rounded)
    flash_k<<<dim3(N_ / 128, H_, B_), tb, SMEM_F>>>(Q, Kp, V, O);

    // 4) out = O Wo + bo
    gemm_mma<<<dim3(16, 128, 1), tb, SMEM_G>>>(O, WoT, out, bo,
        512, 512, 512, 1024, 0, 0, 0, 0, 0, 0, 1, 0);
}

// round 5
// speedup vs baseline: 5.5608x; 1.0527x over previous
#include <cuda_runtime.h>
#include <cstdint>
#include <math.h>

#define B_     4
#define N_     4096
#define M_     1024
#define QD_    1024
#define CD_    768
#define H_     8
#define DH_    64
#define INNER_ 512
#define SCALE_ 0.125f

// ---------------- scratch (__device__ globals; no allocation allowed) -------
__device__ float g_WqT[(size_t)INNER_ * QD_];
__device__ float g_WkT[(size_t)INNER_ * CD_];
__device__ float g_WvT[(size_t)INNER_ * CD_];
__device__ float g_WoT[(size_t)QD_ * INNER_];
__device__ float g_Q  [(size_t)B_ * N_ * INNER_];
__device__ float g_K  [(size_t)B_ * M_ * INNER_];
__device__ float g_V  [(size_t)B_ * M_ * INNER_];
__device__ float g_O  [(size_t)B_ * N_ * INNER_];

// ---------------- helpers ---------------------------------------------------
__device__ __forceinline__ uint32_t smem_u32(const void* p) {
    uint32_t a;
    asm("{ .reg .u64 t; cvta.to.shared.u64 t, %1; cvt.u32.u64 %0, t; }"
        : "=r"(a) : "l"(p));
    return a;
}
__device__ __forceinline__ float rna_tf32(float x) {
    float r; asm("cvt.rna.tf32.f32 %0, %1;" : "=f"(r) : "f"(x)); return r;
}
__device__ __forceinline__ uint32_t ldr(const float* p) {   // load + rna round
    return __float_as_uint(rna_tf32(*p));
}
__device__ __forceinline__ void cp16(uint32_t dst, const void* src) {
    asm volatile("cp.async.cg.shared.global [%0], [%1], 16;"
                 :: "r"(dst), "l"(src) : "memory");
}
__device__ __forceinline__ void mma_tf32_16x8x8(
    float* c, const uint32_t* a, const uint32_t* b) {
    asm volatile(
        "mma.sync.aligned.m16n8k8.row.col.f32.tf32.tf32.f32 "
        "{%0,%1,%2,%3}, {%4,%5,%6,%7}, {%8,%9}, {%0,%1,%2,%3};"
        : "+f"(c[0]), "+f"(c[1]), "+f"(c[2]), "+f"(c[3])
        : "r"(a[0]), "r"(a[1]), "r"(a[2]), "r"(a[3]),
          "r"(b[0]), "r"(b[1]));
}

// ---------------------------------------------------------------------------
// tf32 mma.sync GEMM: C[M,N] = A[M,K] * Bt[N,K]^T  (+bias, optional tf32-round)
// CTA tile 128x128x32, 256 threads (4x2 warps, warp tile 32x64).
// A/B fragments are rna-rounded to tf32 at register load (inputs can be raw fp32).
// Requires M%128==0, N%128==0, K%32==0.
// ---------------------------------------------------------------------------
__global__ __launch_bounds__(256) void gemm_mma(
    const float* __restrict__ A, const float* __restrict__ Bt,
    float* __restrict__ C, const float* __restrict__ bias,
    int K, int lda, int ldb, int ldc, int roundC)
{
    constexpr int BM = 128, BN = 128, BK = 32;
    constexpr int AST = BK + 4;                   // 36 words padded stride
    constexpr int A_WORDS = BM * AST;             // 4608
    constexpr int STAGE_WORDS = (BM + BN) * AST;  // 9216 (36864 B)

    extern __shared__ float sm[];
    const uint32_t sb = smem_u32(sm);

    const int tid = threadIdx.x, wid = tid >> 5, lane = tid & 31;
    const int gid = lane >> 2, tig = lane & 3;
    const int wm = (wid & 3) * 32, wn = (wid >> 2) * 64;

    const int row0 = blockIdx.y * BM;
    const int col0 = blockIdx.x * BN;

    // 8 fixed 16B chunks per thread per k-tile
    const float* ch_g[8];
    uint32_t ch_off[8];
    {
        int q = 0;
        for (int c = tid; c < (BM + BN) * 8; c += 256, q++) {
            if (c < BM * 8) {
                int r = c >> 3, h = c & 7;
                ch_g[q]   = A + (size_t)(row0 + r) * lda + h * 4;
                ch_off[q] = (uint32_t)(r * AST + h * 4) * 4u;
            } else {
                int cb = c - BM * 8, r = cb >> 3, h = cb & 7;
                ch_g[q]   = Bt + (size_t)(col0 + r) * ldb + h * 4;
                ch_off[q] = (uint32_t)(A_WORDS + r * AST + h * 4) * 4u;
            }
        }
    }

    float acc[2][8][4];
#pragma unroll
    for (int mi = 0; mi < 2; mi++)
#pragma unroll
        for (int ni = 0; ni < 8; ni++)
#pragma unroll
            for (int j = 0; j < 4; j++) acc[mi][ni][j] = 0.f;

    const int nt = K >> 5;
#pragma unroll
    for (int q = 0; q < 8; q++) cp16(sb + ch_off[q], ch_g[q]);
    asm volatile("cp.async.commit_group;" ::: "memory");

    for (int kt = 0; kt < nt; kt++) {
        const int s = kt & 1;
        if (kt + 1 < nt) {
            const uint32_t nb = sb + (uint32_t)((s ^ 1) * STAGE_WORDS) * 4u;
#pragma unroll
            for (int q = 0; q < 8; q++)
                cp16(nb + ch_off[q], ch_g[q] + (size_t)(kt + 1) * 32);
            asm volatile("cp.async.commit_group;" ::: "memory");
            asm volatile("cp.async.wait_group 1;" ::: "memory");
        } else {
            asm volatile("cp.async.wait_group 0;" ::: "memory");
        }
        __syncthreads();

        const float* As = sm + s * STAGE_WORDS;
        const float* Bs = As + A_WORDS;
#pragma unroll
        for (int kq = 0; kq < 4; kq++) {
            const int k0 = kq * 8;
            uint32_t a[2][4], b[8][2];
#pragma unroll
            for (int mi = 0; mi < 2; mi++) {
                const float* ap = As + (wm + mi * 16 + gid) * AST + k0 + tig;
                a[mi][0] = ldr(ap);
                a[mi][1] = ldr(ap + 8 * AST);
                a[mi][2] = ldr(ap + 4);
                a[mi][3] = ldr(ap + 8 * AST + 4);
            }
#pragma unroll
            for (int ni = 0; ni < 8; ni++) {
                const float* bp = Bs + (wn + ni * 8 + gid) * AST + k0 + tig;
                b[ni][0] = ldr(bp);
                b[ni][1] = ldr(bp + 4);
            }
#pragma unroll
            for (int mi = 0; mi < 2; mi++)
#pragma unroll
                for (int ni = 0; ni < 8; ni++)
                    mma_tf32_16x8x8(acc[mi][ni], a[mi], b[ni]);
        }
        __syncthreads();
    }

    // epilogue
#pragma unroll
    for (int mi = 0; mi < 2; mi++) {
#pragma unroll
        for (int half = 0; half < 2; half++) {
            const int m = row0 + wm + mi * 16 + gid + half * 8;
            float* crow = C + (size_t)m * ldc + col0 + wn;
#pragma unroll
            for (int ni = 0; ni < 8; ni++) {
                const int cc = ni * 8 + 2 * tig;
                float2 v;
                v.x = acc[mi][ni][half * 2 + 0];
                v.y = acc[mi][ni][half * 2 + 1];
                if (bias) {
                    v.x += bias[col0 + wn + cc + 0];
                    v.y += bias[col0 + wn + cc + 1];
                }
                if (roundC) { v.x = rna_tf32(v.x); v.y = rna_tf32(v.y); }
                *(float2*)(crow + cc) = v;
            }
        }
    }
}

// ---------------------------------------------------------------------------
// Fused flash attention, tf32 mma.sync. CTA: 128 queries of one (b,h).
// 8 warps x 16 rows. KV tiles of 64, cp.async double-buffered. Online softmax.
// ---------------------------------------------------------------------------
__global__ __launch_bounds__(256, 2) void flash_k(
    const float* __restrict__ Q, const float* __restrict__ K,
    const float* __restrict__ V, float* __restrict__ O)
{
    constexpr int PAD = 68;
    constexpr int KV_WORDS = 64 * PAD;
    extern __shared__ float sm[];
    const uint32_t sb = smem_u32(sm);

    const int tid = threadIdx.x, wid = tid >> 5, lane = tid & 31;
    const int gid = lane >> 2, tig = lane & 3;
    const int b = blockIdx.z, h = blockIdx.y, q0 = blockIdx.x * 128;
    const int wrow = wid * 16;

    const float* Qg = Q + ((size_t)(b * N_ + q0)) * INNER_ + h * DH_;
    const float* Kg = K + ((size_t)b * M_) * INNER_ + h * DH_;
    const float* Vg = V + ((size_t)b * M_) * INNER_ + h * DH_;
    float*       Og = O + ((size_t)(b * N_ + q0)) * INNER_ + h * DH_;

    float* Ksm = sm;
    float* Vsm = sm + 2 * KV_WORDS;
    float* QP  = sm + 4 * KV_WORDS;

    const int lr = tid >> 4, lch = tid & 15;

#pragma unroll
    for (int i = 0; i < 8; i++) {
        const int row = i * 16 + lr;
        cp16(sb + (uint32_t)((4 * KV_WORDS + row * PAD + lch * 4) * 4),
             Qg + (size_t)row * INNER_ + lch * 4);
    }
    asm volatile("cp.async.commit_group;" ::: "memory");
    asm volatile("cp.async.wait_group 0;" ::: "memory");
    __syncthreads();

    uint32_t aq[8][4];
#pragma unroll
    for (int kq = 0; kq < 8; kq++) {
        const float* qp = QP + (wrow + gid) * PAD + kq * 8 + tig;
        aq[kq][0] = __float_as_uint(qp[0]);
        aq[kq][1] = __float_as_uint(qp[8 * PAD]);
        aq[kq][2] = __float_as_uint(qp[4]);
        aq[kq][3] = __float_as_uint(qp[8 * PAD + 4]);
    }

    float oacc[8][4];
#pragma unroll
    for (int ni = 0; ni < 8; ni++)
#pragma unroll
        for (int j = 0; j < 4; j++) oacc[ni][j] = 0.f;
    float m0 = -1e30f, m1 = -1e30f, l0 = 0.f, l1 = 0.f;

    auto prefetch = [&](int t, int s) {
#pragma unroll
        for (int q = 0; q < 4; q++) {
            const int row = q * 16 + lr;
            const uint32_t so = (uint32_t)(((s * 64 + row) * PAD + lch * 4) * 4);
            const size_t go = (size_t)(t * 64 + row) * INNER_ + lch * 4;
            cp16(sb + so, Kg + go);
            cp16(sb + (uint32_t)(2 * KV_WORDS * 4) + so, Vg + go);
        }
        asm volatile("cp.async.commit_group;" ::: "memory");
    };
    prefetch(0, 0);

    for (int t = 0; t < M_ / 64; t++) {
        const int s = t & 1;
        if (t + 1 < M_ / 64) {
            prefetch(t + 1, s ^ 1);
            asm volatile("cp.async.wait_group 1;" ::: "memory");
        } else {
            asm volatile("cp.async.wait_group 0;" ::: "memory");
        }
        __syncthreads();

        const float* Ks = Ksm + s * KV_WORDS;
        const float* Vs = Vsm + s * KV_WORDS;

        float sacc[8][4];
#pragma unroll
        for (int ni = 0; ni < 8; ni++)
#pragma unroll
            for (int j = 0; j < 4; j++) sacc[ni][j] = 0.f;
#pragma unroll
        for (int kq = 0; kq < 8; kq++) {
#pragma unroll
            for (int ni = 0; ni < 8; ni++) {
                const float* kp = Ks + (ni * 8 + gid) * PAD + kq * 8 + tig;
                uint32_t bb[2] = { __float_as_uint(kp[0]), __float_as_uint(kp[4]) };
                mma_tf32_16x8x8(sacc[ni], aq[kq], bb);
            }
        }

        float r0m = -1e30f, r1m = -1e30f;
#pragma unroll
        for (int ni = 0; ni < 8; ni++) {
#pragma unroll
            for (int j = 0; j < 4; j++) sacc[ni][j] *= SCALE_;
            r0m = fmaxf(r0m, fmaxf(sacc[ni][0], sacc[ni][1]));
            r1m = fmaxf(r1m, fmaxf(sacc[ni][2], sacc[ni][3]));
        }
        r0m = fmaxf(r0m, __shfl_xor_sync(~0u, r0m, 1));
        r0m = fmaxf(r0m, __shfl_xor_sync(~0u, r0m, 2));
        r1m = fmaxf(r1m, __shfl_xor_sync(~0u, r1m, 1));
        r1m = fmaxf(r1m, __shfl_xor_sync(~0u, r1m, 2));
        const float nm0 = fmaxf(m0, r0m), nm1 = fmaxf(m1, r1m);
        const float c0 = __expf(m0 - nm0), c1 = __expf(m1 - nm1);
        float s0 = 0.f, s1 = 0.f;
        float* Pw = QP + wrow * PAD;
#pragma unroll
        for (int ni = 0; ni < 8; ni++) {
            const float p0 = __expf(sacc[ni][0] - nm0);
            const float p1 = __expf(sacc[ni][1] - nm0);
            const float p2 = __expf(sacc[ni][2] - nm1);
            const float p3 = __expf(sacc[ni][3] - nm1);
            s0 += p0 + p1; s1 += p2 + p3;
            float2 v0 = make_float2(rna_tf32(p0), rna_tf32(p1));
            float2 v1 = make_float2(rna_tf32(p2), rna_tf32(p3));
            *(float2*)(Pw + gid * PAD + ni * 8 + 2 * tig) = v0;
            *(float2*)(Pw + (gid + 8) * PAD + ni * 8 + 2 * tig) = v1;
        }
        s0 += __shfl_xor_sync(~0u, s0, 1); s0 += __shfl_xor_sync(~0u, s0, 2);
        s1 += __shfl_xor_sync(~0u, s1, 1); s1 += __shfl_xor_sync(~0u, s1, 2);
        l0 = l0 * c0 + s0; l1 = l1 * c1 + s1;
        m0 = nm0; m1 = nm1;
#pragma unroll
        for (int ni = 0; ni < 8; ni++) {
            oacc[ni][0] *= c0; oacc[ni][1] *= c0;
            oacc[ni][2] *= c1; oacc[ni][3] *= c1;
        }
        __syncwarp();

#pragma unroll
        for (int kq = 0; kq < 8; kq++) {
            const float* pp = Pw + gid * PAD + kq * 8 + tig;
            uint32_t ap[4] = {
                __float_as_uint(pp[0]), __float_as_uint(pp[8 * PAD]),
                __float_as_uint(pp[4]), __float_as_uint(pp[8 * PAD + 4]) };
#pragma unroll
            for (int ni = 0; ni < 8; ni++) {
                const float* vp = Vs + (kq * 8 + tig) * PAD + ni * 8 + gid;
                uint32_t bb[2] = { __float_as_uint(vp[0]),
                                   __float_as_uint(vp[4 * PAD]) };
                mma_tf32_16x8x8(oacc[ni], ap, bb);
            }
        }
        __syncwarp();
        __syncthreads();
    }

    const float inv0 = 1.f / l0, inv1 = 1.f / l1;
#pragma unroll
    for (int ni = 0; ni < 8; ni++) {
        const int cc = ni * 8 + 2 * tig;
        float2 v0 = make_float2(rna_tf32(oacc[ni][0] * inv0),
                                rna_tf32(oacc[ni][1] * inv0));
        float2 v1 = make_float2(rna_tf32(oacc[ni][2] * inv1),
                                rna_tf32(oacc[ni][3] * inv1));
        *(float2*)(Og + (size_t)(wrow + gid) * INNER_ + cc) = v0;
        *(float2*)(Og + (size_t)(wrow + gid + 8) * INNER_ + cc) = v1;
    }
}

// ---------------------------------------------------------------------------
__global__ void transpose_k(const float* __restrict__ in, float* __restrict__ out,
                            int rows, int cols, int ldin, int ldout)
{
    __shared__ float t[32][33];
    const int c0 = blockIdx.x * 32, r0 = blockIdx.y * 32;
    const int x = threadIdx.x, y = threadIdx.y;
    for (int i = y; i < 32; i += 8) {
        int r = r0 + i, c = c0 + x;
        t[i][x] = (r < rows && c < cols) ? in[(size_t)r * ldin + c] : 0.f;
    }
    __syncthreads();
    for (int i = y; i < 32; i += 8) {
        int orow = c0 + i, oc = r0 + x;
        if (orow < cols && oc < rows)
            out[(size_t)orow * ldout + oc] = rna_tf32(t[x][i]);
    }
}

// ---------------------------------------------------------------------------
extern "C" void kernel_launch(void* const* d_in, const int* in_sizes, int n_in,
                              void* d_out, int out_size)
{
    const float* x   = (const float*)d_in[0];
    const float* ctx = (const float*)d_in[1];
    const float* Wq  = (const float*)d_in[2];
    const float* Wk  = (const float*)d_in[3];
    const float* Wv  = (const float*)d_in[4];
    const float* Wo  = (const float*)d_in[5];
    const float* bo  = (const float*)d_in[6];
    float* out = (float*)d_out;

    float *WqT, *WkT, *WvT, *WoT, *Q, *Kp, *V, *O;
    cudaGetSymbolAddress((void**)&WqT, g_WqT);
    cudaGetSymbolAddress((void**)&WkT, g_WkT);
    cudaGetSymbolAddress((void**)&WvT, g_WvT);
    cudaGetSymbolAddress((void**)&WoT, g_WoT);
    cudaGetSymbolAddress((void**)&Q,   g_Q);
    cudaGetSymbolAddress((void**)&Kp,  g_K);
    cudaGetSymbolAddress((void**)&V,   g_V);
    cudaGetSymbolAddress((void**)&O,   g_O);

    const int SMEM_G = 2 * (128 + 128) * 36 * 4;           // 73728 B
    const int SMEM_F = (4 * 64 * 68 + 128 * 68) * 4;       // 104448 B
    cudaFuncSetAttribute(gemm_mma, cudaFuncAttributeMaxDynamicSharedMemorySize, SMEM_G);
    cudaFuncSetAttribute(flash_k,  cudaFuncAttributeMaxDynamicSharedMemorySize, SMEM_F);

    const dim3 tb(256);
    dim3 t32(32, 8);

    // 1) weight transposes (tf32-rounded)
    transpose_k<<<dim3(16, 32), t32>>>(Wq, WqT, 1024, 512, 512, 1024);
    transpose_k<<<dim3(16, 24), t32>>>(Wk, WkT,  768, 512, 512,  768);
    transpose_k<<<dim3(16, 24), t32>>>(Wv, WvT,  768, 512, 512,  768);
    transpose_k<<<dim3(32, 16), t32>>>(Wo, WoT,  512, 1024, 1024, 512);

    // 2) projections (raw inputs; fragments rounded in-register; outputs rounded)
    gemm_mma<<<dim3(4, 128), tb, SMEM_G>>>(x,   WqT, Q,  nullptr, 1024, 1024, 1024, 512, 1);
    gemm_mma<<<dim3(4, 32),  tb, SMEM_G>>>(ctx, WkT, Kp, nullptr,  768,  768,  768, 512, 1);
    gemm_mma<<<dim3(4, 32),  tb, SMEM_G>>>(ctx, WvT, V,  nullptr,  768,  768,  768, 512, 1);

    // 3) fused flash attention -> O (rounded)
    flash_k<<<dim3(N_ / 128, H_, B_), tb, SMEM_F>>>(Q, Kp, V, O);

    // 4) out = O Wo + bo
    gemm_mma<<<dim3(8, 128), tb, SMEM_G>>>(O, WoT, out, bo, 512, 512, 512, 1024, 0);
}

// round 6
// speedup vs baseline: 5.6920x; 1.0236x over previous
#include <cuda_runtime.h>
#include <cstdint>
#include <math.h>

#define B_     4
#define N_     4096
#define M_     1024
#define QD_    1024
#define CD_    768
#define H_     8
#define DH_    64
#define INNER_ 512
#define SCALE_ 0.125f

// ---------------- scratch (__device__ globals; no allocation allowed) -------
__device__ float g_WqT[(size_t)INNER_ * QD_];
__device__ float g_WkT[(size_t)INNER_ * CD_];
__device__ float g_WvT[(size_t)INNER_ * CD_];
__device__ float g_WoT[(size_t)QD_ * INNER_];
__device__ float g_Q  [(size_t)B_ * N_ * INNER_];
__device__ float g_K  [(size_t)B_ * M_ * INNER_];
__device__ float g_V  [(size_t)B_ * M_ * INNER_];
__device__ float g_O  [(size_t)B_ * N_ * INNER_];

// ---------------- helpers ---------------------------------------------------
__device__ __forceinline__ uint32_t smem_u32(const void* p) {
    uint32_t a;
    asm("{ .reg .u64 t; cvta.to.shared.u64 t, %1; cvt.u32.u64 %0, t; }"
        : "=r"(a) : "l"(p));
    return a;
}
__device__ __forceinline__ float rna_tf32(float x) {
    float r; asm("cvt.rna.tf32.f32 %0, %1;" : "=f"(r) : "f"(x)); return r;
}
__device__ __forceinline__ uint32_t ldr(const float* p) {   // load + rna round
    return __float_as_uint(rna_tf32(*p));
}
__device__ __forceinline__ void cp16(uint32_t dst, const void* src) {
    asm volatile("cp.async.cg.shared.global [%0], [%1], 16;"
                 :: "r"(dst), "l"(src) : "memory");
}
__device__ __forceinline__ void mma_tf32_16x8x8(
    float* c, const uint32_t* a, const uint32_t* b) {
    asm volatile(
        "mma.sync.aligned.m16n8k8.row.col.f32.tf32.tf32.f32 "
        "{%0,%1,%2,%3}, {%4,%5,%6,%7}, {%8,%9}, {%0,%1,%2,%3};"
        : "+f"(c[0]), "+f"(c[1]), "+f"(c[2]), "+f"(c[3])
        : "r"(a[0]), "r"(a[1]), "r"(a[2]), "r"(a[3]),
          "r"(b[0]), "r"(b[1]));
}

// ---------------------------------------------------------------------------
// tf32 mma.sync GEMM: C[M,N] = A[M,K] * Bt[N,K]^T  (+bias, optional tf32-round)
// CTA tile 128x128x32, 128 threads = 4 warps, warp tile 64x64 (LDS/MMA = 1.0).
// Fragments rna-rounded to tf32 at register load. M%128==0, N%128==0, K%32==0.
// ---------------------------------------------------------------------------
__global__ __launch_bounds__(128) void gemm_mma(
    const float* __restrict__ A, const float* __restrict__ Bt,
    float* __restrict__ C, const float* __restrict__ bias,
    int K, int lda, int ldb, int ldc, int roundC)
{
    constexpr int BM = 128, BN = 128;
    constexpr int AST = 36;                       // padded stride (words)
    constexpr int A_WORDS = BM * AST;             // 4608
    constexpr int STAGE_WORDS = (BM + BN) * AST;  // 9216 words (36864 B)

    extern __shared__ float sm[];
    const uint32_t sb = smem_u32(sm);

    const int tid = threadIdx.x, wid = tid >> 5, lane = tid & 31;
    const int gid = lane >> 2, tig = lane & 3;
    const int wm = (wid & 1) * 64, wn = (wid >> 1) * 64;

    const int row0 = blockIdx.y * BM;
    const int col0 = blockIdx.x * BN;

    // loader: thread owns rows lr+16q (q=0..7), 16B chunk lh, for both A and B
    const int lr = tid >> 3;            // 0..15
    const int lh = tid & 7;             // 0..7
    const float* Ag = A + (size_t)(row0 + lr) * lda + lh * 4;
    const float* Bg = Bt + (size_t)(col0 + lr) * ldb + lh * 4;
    const uint32_t aoff = (uint32_t)((lr * AST + lh * 4) * 4);
    const uint32_t boff = (uint32_t)((A_WORDS + lr * AST + lh * 4) * 4);

    float acc[4][8][4];
#pragma unroll
    for (int mi = 0; mi < 4; mi++)
#pragma unroll
        for (int ni = 0; ni < 8; ni++)
#pragma unroll
            for (int j = 0; j < 4; j++) acc[mi][ni][j] = 0.f;

    const int nt = K >> 5;

    // prefetch k-tile 0 into stage 0
    {
#pragma unroll
        for (int q = 0; q < 8; q++) {
            cp16(sb + aoff + (uint32_t)(q * 16 * AST * 4), Ag + (size_t)q * 16 * lda);
            cp16(sb + boff + (uint32_t)(q * 16 * AST * 4), Bg + (size_t)q * 16 * ldb);
        }
        asm volatile("cp.async.commit_group;" ::: "memory");
    }

    for (int kt = 0; kt < nt; kt++) {
        const int s = kt & 1;
        if (kt + 1 < nt) {
            const uint32_t st = sb + (uint32_t)((s ^ 1) * STAGE_WORDS) * 4u;
            const size_t ko = (size_t)(kt + 1) * 32;
#pragma unroll
            for (int q = 0; q < 8; q++) {
                cp16(st + aoff + (uint32_t)(q * 16 * AST * 4),
                     Ag + (size_t)q * 16 * lda + ko);
                cp16(st + boff + (uint32_t)(q * 16 * AST * 4),
                     Bg + (size_t)q * 16 * ldb + ko);
            }
            asm volatile("cp.async.commit_group;" ::: "memory");
            asm volatile("cp.async.wait_group 1;" ::: "memory");
        } else {
            asm volatile("cp.async.wait_group 0;" ::: "memory");
        }
        __syncthreads();

        const float* As = sm + s * STAGE_WORDS;
        const float* Bs = As + A_WORDS;
#pragma unroll
        for (int kq = 0; kq < 4; kq++) {
            const int k0 = kq * 8;
            uint32_t a[4][4], b[8][2];
#pragma unroll
            for (int mi = 0; mi < 4; mi++) {
                const float* ap = As + (wm + mi * 16 + gid) * AST + k0 + tig;
                a[mi][0] = ldr(ap);
                a[mi][1] = ldr(ap + 8 * AST);
                a[mi][2] = ldr(ap + 4);
                a[mi][3] = ldr(ap + 8 * AST + 4);
            }
#pragma unroll
            for (int ni = 0; ni < 8; ni++) {
                const float* bp = Bs + (wn + ni * 8 + gid) * AST + k0 + tig;
                b[ni][0] = ldr(bp);
                b[ni][1] = ldr(bp + 4);
            }
#pragma unroll
            for (int mi = 0; mi < 4; mi++)
#pragma unroll
                for (int ni = 0; ni < 8; ni++)
                    mma_tf32_16x8x8(acc[mi][ni], a[mi], b[ni]);
        }
        __syncthreads();
    }

    // epilogue
#pragma unroll
    for (int mi = 0; mi < 4; mi++) {
#pragma unroll
        for (int half = 0; half < 2; half++) {
            const int m = row0 + wm + mi * 16 + gid + half * 8;
            float* crow = C + (size_t)m * ldc + col0 + wn;
#pragma unroll
            for (int ni = 0; ni < 8; ni++) {
                const int cc = ni * 8 + 2 * tig;
                float2 v;
                v.x = acc[mi][ni][half * 2 + 0];
                v.y = acc[mi][ni][half * 2 + 1];
                if (bias) {
                    v.x += bias[col0 + wn + cc + 0];
                    v.y += bias[col0 + wn + cc + 1];
                }
                if (roundC) { v.x = rna_tf32(v.x); v.y = rna_tf32(v.y); }
                *(float2*)(crow + cc) = v;
            }
        }
    }
}

// ---------------------------------------------------------------------------
// Fused flash attention, tf32 mma.sync. CTA: 128 queries of one (b,h).
// 8 warps x 16 rows. KV tiles of 64, cp.async double-buffered. Online softmax.
// ---------------------------------------------------------------------------
__global__ __launch_bounds__(256, 2) void flash_k(
    const float* __restrict__ Q, const float* __restrict__ K,
    const float* __restrict__ V, float* __restrict__ O)
{
    constexpr int PAD = 68;
    constexpr int KV_WORDS = 64 * PAD;
    extern __shared__ float sm[];
    const uint32_t sb = smem_u32(sm);

    const int tid = threadIdx.x, wid = tid >> 5, lane = tid & 31;
    const int gid = lane >> 2, tig = lane & 3;
    const int b = blockIdx.z, h = blockIdx.y, q0 = blockIdx.x * 128;
    const int wrow = wid * 16;

    const float* Qg = Q + ((size_t)(b * N_ + q0)) * INNER_ + h * DH_;
    const float* Kg = K + ((size_t)b * M_) * INNER_ + h * DH_;
    const float* Vg = V + ((size_t)b * M_) * INNER_ + h * DH_;
    float*       Og = O + ((size_t)(b * N_ + q0)) * INNER_ + h * DH_;

    float* Ksm = sm;
    float* Vsm = sm + 2 * KV_WORDS;
    float* QP  = sm + 4 * KV_WORDS;

    const int lr = tid >> 4, lch = tid & 15;

#pragma unroll
    for (int i = 0; i < 8; i++) {
        const int row = i * 16 + lr;
        cp16(sb + (uint32_t)((4 * KV_WORDS + row * PAD + lch * 4) * 4),
             Qg + (size_t)row * INNER_ + lch * 4);
    }
    asm volatile("cp.async.commit_group;" ::: "memory");
    asm volatile("cp.async.wait_group 0;" ::: "memory");
    __syncthreads();

    uint32_t aq[8][4];
#pragma unroll
    for (int kq = 0; kq < 8; kq++) {
        const float* qp = QP + (wrow + gid) * PAD + kq * 8 + tig;
        aq[kq][0] = __float_as_uint(qp[0]);
        aq[kq][1] = __float_as_uint(qp[8 * PAD]);
        aq[kq][2] = __float_as_uint(qp[4]);
        aq[kq][3] = __float_as_uint(qp[8 * PAD + 4]);
    }

    float oacc[8][4];
#pragma unroll
    for (int ni = 0; ni < 8; ni++)
#pragma unroll
        for (int j = 0; j < 4; j++) oacc[ni][j] = 0.f;
    float m0 = -1e30f, m1 = -1e30f, l0 = 0.f, l1 = 0.f;

    auto prefetch = [&](int t, int s) {
#pragma unroll
        for (int q = 0; q < 4; q++) {
            const int row = q * 16 + lr;
            const uint32_t so = (uint32_t)(((s * 64 + row) * PAD + lch * 4) * 4);
            const size_t go = (size_t)(t * 64 + row) * INNER_ + lch * 4;
            cp16(sb + so, Kg + go);
            cp16(sb + (uint32_t)(2 * KV_WORDS * 4) + so, Vg + go);
        }
        asm volatile("cp.async.commit_group;" ::: "memory");
    };
    prefetch(0, 0);

    for (int t = 0; t < M_ / 64; t++) {
        const int s = t & 1;
        if (t + 1 < M_ / 64) {
            prefetch(t + 1, s ^ 1);
            asm volatile("cp.async.wait_group 1;" ::: "memory");
        } else {
            asm volatile("cp.async.wait_group 0;" ::: "memory");
        }
        __syncthreads();

        const float* Ks = Ksm + s * KV_WORDS;
        const float* Vs = Vsm + s * KV_WORDS;

        float sacc[8][4];
#pragma unroll
        for (int ni = 0; ni < 8; ni++)
#pragma unroll
            for (int j = 0; j < 4; j++) sacc[ni][j] = 0.f;
#pragma unroll
        for (int kq = 0; kq < 8; kq++) {
#pragma unroll
            for (int ni = 0; ni < 8; ni++) {
                const float* kp = Ks + (ni * 8 + gid) * PAD + kq * 8 + tig;
                uint32_t bb[2] = { __float_as_uint(kp[0]), __float_as_uint(kp[4]) };
                mma_tf32_16x8x8(sacc[ni], aq[kq], bb);
            }
        }

        float r0m = -1e30f, r1m = -1e30f;
#pragma unroll
        for (int ni = 0; ni < 8; ni++) {
#pragma unroll
            for (int j = 0; j < 4; j++) sacc[ni][j] *= SCALE_;
            r0m = fmaxf(r0m, fmaxf(sacc[ni][0], sacc[ni][1]));
            r1m = fmaxf(r1m, fmaxf(sacc[ni][2], sacc[ni][3]));
        }
        r0m = fmaxf(r0m, __shfl_xor_sync(~0u, r0m, 1));
        r0m = fmaxf(r0m, __shfl_xor_sync(~0u, r0m, 2));
        r1m = fmaxf(r1m, __shfl_xor_sync(~0u, r1m, 1));
        r1m = fmaxf(r1m, __shfl_xor_sync(~0u, r1m, 2));
        const float nm0 = fmaxf(m0, r0m), nm1 = fmaxf(m1, r1m);
        const float c0 = __expf(m0 - nm0), c1 = __expf(m1 - nm1);
        float s0 = 0.f, s1 = 0.f;
        float* Pw = QP + wrow * PAD;
#pragma unroll
        for (int ni = 0; ni < 8; ni++) {
            const float p0 = __expf(sacc[ni][0] - nm0);
            const float p1 = __expf(sacc[ni][1] - nm0);
            const float p2 = __expf(sacc[ni][2] - nm1);
            const float p3 = __expf(sacc[ni][3] - nm1);
            s0 += p0 + p1; s1 += p2 + p3;
            float2 v0 = make_float2(rna_tf32(p0), rna_tf32(p1));
            float2 v1 = make_float2(rna_tf32(p2), rna_tf32(p3));
            *(float2*)(Pw + gid * PAD + ni * 8 + 2 * tig) = v0;
            *(float2*)(Pw + (gid + 8) * PAD + ni * 8 + 2 * tig) = v1;
        }
        s0 += __shfl_xor_sync(~0u, s0, 1); s0 += __shfl_xor_sync(~0u, s0, 2);
        s1 += __shfl_xor_sync(~0u, s1, 1); s1 += __shfl_xor_sync(~0u, s1, 2);
        l0 = l0 * c0 + s0; l1 = l1 * c1 + s1;
        m0 = nm0; m1 = nm1;
#pragma unroll
        for (int ni = 0; ni < 8; ni++) {
            oacc[ni][0] *= c0; oacc[ni][1] *= c0;
            oacc[ni][2] *= c1; oacc[ni][3] *= c1;
        }
        __syncwarp();

#pragma unroll
        for (int kq = 0; kq < 8; kq++) {
            const float* pp = Pw + gid * PAD + kq * 8 + tig;
            uint32_t ap[4] = {
                __float_as_uint(pp[0]), __float_as_uint(pp[8 * PAD]),
                __float_as_uint(pp[4]), __float_as_uint(pp[8 * PAD + 4]) };
#pragma unroll
            for (int ni = 0; ni < 8; ni++) {
                const float* vp = Vs + (kq * 8 + tig) * PAD + ni * 8 + gid;
                uint32_t bb[2] = { __float_as_uint(vp[0]),
                                   __float_as_uint(vp[4 * PAD]) };
                mma_tf32_16x8x8(oacc[ni], ap, bb);
            }
        }
        __syncwarp();
        __syncthreads();
    }

    const float inv0 = 1.f / l0, inv1 = 1.f / l1;
#pragma unroll
    for (int ni = 0; ni < 8; ni++) {
        const int cc = ni * 8 + 2 * tig;
        float2 v0 = make_float2(rna_tf32(oacc[ni][0] * inv0),
                                rna_tf32(oacc[ni][1] * inv0));
        float2 v1 = make_float2(rna_tf32(oacc[ni][2] * inv1),
                                rna_tf32(oacc[ni][3] * inv1));
        *(float2*)(Og + (size_t)(wrow + gid) * INNER_ + cc) = v0;
        *(float2*)(Og + (size_t)(wrow + gid + 8) * INNER_ + cc) = v1;
    }
}

// ---------------------------------------------------------------------------
// all 4 weight transposes in one launch (z selects weight), tf32-rounded
// ---------------------------------------------------------------------------
__global__ void transpose_all(
    const float* __restrict__ Wq, const float* __restrict__ Wk,
    const float* __restrict__ Wv, const float* __restrict__ Wo,
    float* __restrict__ WqT, float* __restrict__ WkT,
    float* __restrict__ WvT, float* __restrict__ WoT)
{
    __shared__ float t[32][33];
    const int z = blockIdx.z;
    const float* in; float* out; int rows, cols;
    if      (z == 0) { in = Wq; out = WqT; rows = 1024; cols = 512; }
    else if (z == 1) { in = Wk; out = WkT; rows = 768;  cols = 512; }
    else if (z == 2) { in = Wv; out = WvT; rows = 768;  cols = 512; }
    else             { in = Wo; out = WoT; rows = 512;  cols = 1024; }

    const int c0 = blockIdx.x * 32, r0 = blockIdx.y * 32;
    if (c0 >= cols || r0 >= rows) return;
    const int x = threadIdx.x, y = threadIdx.y;
    for (int i = y; i < 32; i += 8) {
        int r = r0 + i, c = c0 + x;
        t[i][x] = (r < rows && c < cols) ? in[(size_t)r * cols + c] : 0.f;
    }
    __syncthreads();
    for (int i = y; i < 32; i += 8) {
        int orow = c0 + i, oc = r0 + x;
        if (orow < cols && oc < rows)
            out[(size_t)orow * rows + oc] = rna_tf32(t[x][i]);
    }
}

// ---------------------------------------------------------------------------
extern "C" void kernel_launch(void* const* d_in, const int* in_sizes, int n_in,
                              void* d_out, int out_size)
{
    const float* x   = (const float*)d_in[0];
    const float* ctx = (const float*)d_in[1];
    const float* Wq  = (const float*)d_in[2];
    const float* Wk  = (const float*)d_in[3];
    const float* Wv  = (const float*)d_in[4];
    const float* Wo  = (const float*)d_in[5];
    const float* bo  = (const float*)d_in[6];
    float* out = (float*)d_out;

    float *WqT, *WkT, *WvT, *WoT, *Q, *Kp, *V, *O;
    cudaGetSymbolAddress((void**)&WqT, g_WqT);
    cudaGetSymbolAddress((void**)&WkT, g_WkT);
    cudaGetSymbolAddress((void**)&WvT, g_WvT);
    cudaGetSymbolAddress((void**)&WoT, g_WoT);
    cudaGetSymbolAddress((void**)&Q,   g_Q);
    cudaGetSymbolAddress((void**)&Kp,  g_K);
    cudaGetSymbolAddress((void**)&V,   g_V);
    cudaGetSymbolAddress((void**)&O,   g_O);

    const int SMEM_G = 2 * (128 + 128) * 36 * 4;           // 73728 B
    const int SMEM_F = (4 * 64 * 68 + 128 * 68) * 4;       // 104448 B
    cudaFuncSetAttribute(gemm_mma, cudaFuncAttributeMaxDynamicSharedMemorySize, SMEM_G);
    cudaFuncSetAttribute(flash_k,  cudaFuncAttributeMaxDynamicSharedMemorySize, SMEM_F);

    // 1) all weight transposes in one launch (tf32-rounded)
    transpose_all<<<dim3(32, 32, 4), dim3(32, 8)>>>(Wq, Wk, Wv, Wo,
                                                    WqT, WkT, WvT, WoT);

    // 2) projections (raw inputs; fragments rounded in-register; outputs rounded)
    gemm_mma<<<dim3(4, 128), 128, SMEM_G>>>(x,   WqT, Q,  nullptr, 1024, 1024, 1024, 512, 1);
    gemm_mma<<<dim3(4, 32),  128, SMEM_G>>>(ctx, WkT, Kp, nullptr,  768,  768,  768, 512, 1);
    gemm_mma<<<dim3(4, 32),  128, SMEM_G>>>(ctx, WvT, V,  nullptr,  768,  768,  768, 512, 1);

    // 3) fused flash attention -> O (rounded)
    flash_k<<<dim3(N_ / 128, H_, B_), 256, SMEM_F>>>(Q, Kp, V, O);

    // 4) out = O Wo + bo
    gemm_mma<<<dim3(8, 128), 128, SMEM_G>>>(O, WoT, out, bo, 512, 512, 512, 1024, 0);
}

// round 7
// speedup vs baseline: 6.4021x; 1.1248x over previous
#include <cuda_runtime.h>
#include <cstdint>
#include <math.h>

#define B_     4
#define N_     4096
#define M_     1024
#define QD_    1024
#define CD_    768
#define H_     8
#define DH_    64
#define INNER_ 512
#define SCALE_ 0.125f
#define LDKV_  1024

// ---------------- scratch (__device__ globals; no allocation allowed) -------
__device__ float g_WqT [(size_t)INNER_ * QD_];
__device__ float g_WkvT[(size_t)2 * INNER_ * CD_];   // rows 0-511: WkT, 512-1023: WvT
__device__ float g_WoT [(size_t)QD_ * INNER_];
__device__ float g_Q   [(size_t)B_ * N_ * INNER_];
__device__ float g_KV  [(size_t)B_ * M_ * LDKV_];    // cols 0-511: K, 512-1023: V
__device__ float g_O   [(size_t)B_ * N_ * INNER_];

// ---------------- helpers ---------------------------------------------------
__device__ __forceinline__ uint32_t smem_u32(const void* p) {
    uint32_t a;
    asm("{ .reg .u64 t; cvta.to.shared.u64 t, %1; cvt.u32.u64 %0, t; }"
        : "=r"(a) : "l"(p));
    return a;
}
__device__ __forceinline__ float rna_tf32(float x) {
    float r; asm("cvt.rna.tf32.f32 %0, %1;" : "=f"(r) : "f"(x)); return r;
}
__device__ __forceinline__ uint32_t ldr(const float* p) {
    return __float_as_uint(rna_tf32(*p));
}
__device__ __forceinline__ void cp16(uint32_t dst, const void* src) {
    asm volatile("cp.async.cg.shared.global [%0], [%1], 16;"
                 :: "r"(dst), "l"(src) : "memory");
}
__device__ __forceinline__ void mma_tf32_16x8x8(
    float* c, const uint32_t* a, const uint32_t* b) {
    asm volatile(
        "mma.sync.aligned.m16n8k8.row.col.f32.tf32.tf32.f32 "
        "{%0,%1,%2,%3}, {%4,%5,%6,%7}, {%8,%9}, {%0,%1,%2,%3};"
        : "+f"(c[0]), "+f"(c[1]), "+f"(c[2]), "+f"(c[3])
        : "r"(a[0]), "r"(a[1]), "r"(a[2]), "r"(a[3]),
          "r"(b[0]), "r"(b[1]));
}

// ---------------------------------------------------------------------------
// tf32 mma.sync GEMM: C[M,N] = A[M,K] * Bt[N,K]^T  (+bias, optional tf32-round)
// CTA tile 128x128x32, 128 threads = 4 warps, warp tile 64x64.
// __launch_bounds__(128,3): pin regs <=170 so 3 CTAs/SM co-reside.
// ---------------------------------------------------------------------------
__global__ __launch_bounds__(128, 3) void gemm_mma(
    const float* __restrict__ A, const float* __restrict__ Bt,
    float* __restrict__ C, const float* __restrict__ bias,
    int K, int lda, int ldb, int ldc, int roundC)
{
    constexpr int BM = 128, BN = 128;
    constexpr int AST = 36;
    constexpr int A_WORDS = BM * AST;
    constexpr int STAGE_WORDS = (BM + BN) * AST;

    extern __shared__ float sm[];
    const uint32_t sb = smem_u32(sm);

    const int tid = threadIdx.x, wid = tid >> 5, lane = tid & 31;
    const int gid = lane >> 2, tig = lane & 3;
    const int wm = (wid & 1) * 64, wn = (wid >> 1) * 64;

    const int row0 = blockIdx.y * BM;
    const int col0 = blockIdx.x * BN;

    const int lr = tid >> 3;            // 0..15
    const int lh = tid & 7;             // 0..7
    const float* Ag = A + (size_t)(row0 + lr) * lda + lh * 4;
    const float* Bg = Bt + (size_t)(col0 + lr) * ldb + lh * 4;
    const uint32_t aoff = (uint32_t)((lr * AST + lh * 4) * 4);
    const uint32_t boff = (uint32_t)((A_WORDS + lr * AST + lh * 4) * 4);

    float acc[4][8][4];
#pragma unroll
    for (int mi = 0; mi < 4; mi++)
#pragma unroll
        for (int ni = 0; ni < 8; ni++)
#pragma unroll
            for (int j = 0; j < 4; j++) acc[mi][ni][j] = 0.f;

    const int nt = K >> 5;
    {
#pragma unroll
        for (int q = 0; q < 8; q++) {
            cp16(sb + aoff + (uint32_t)(q * 16 * AST * 4), Ag + (size_t)q * 16 * lda);
            cp16(sb + boff + (uint32_t)(q * 16 * AST * 4), Bg + (size_t)q * 16 * ldb);
        }
        asm volatile("cp.async.commit_group;" ::: "memory");
    }

    for (int kt = 0; kt < nt; kt++) {
        const int s = kt & 1;
        if (kt + 1 < nt) {
            const uint32_t st = sb + (uint32_t)((s ^ 1) * STAGE_WORDS) * 4u;
            const size_t ko = (size_t)(kt + 1) * 32;
#pragma unroll
            for (int q = 0; q < 8; q++) {
                cp16(st + aoff + (uint32_t)(q * 16 * AST * 4),
                     Ag + (size_t)q * 16 * lda + ko);
                cp16(st + boff + (uint32_t)(q * 16 * AST * 4),
                     Bg + (size_t)q * 16 * ldb + ko);
            }
            asm volatile("cp.async.commit_group;" ::: "memory");
            asm volatile("cp.async.wait_group 1;" ::: "memory");
        } else {
            asm volatile("cp.async.wait_group 0;" ::: "memory");
        }
        __syncthreads();

        const float* As = sm + s * STAGE_WORDS;
        const float* Bs = As + A_WORDS;
#pragma unroll
        for (int kq = 0; kq < 4; kq++) {
            const int k0 = kq * 8;
            uint32_t a[4][4], b[8][2];
#pragma unroll
            for (int mi = 0; mi < 4; mi++) {
                const float* ap = As + (wm + mi * 16 + gid) * AST + k0 + tig;
                a[mi][0] = ldr(ap);
                a[mi][1] = ldr(ap + 8 * AST);
                a[mi][2] = ldr(ap + 4);
                a[mi][3] = ldr(ap + 8 * AST + 4);
            }
#pragma unroll
            for (int ni = 0; ni < 8; ni++) {
                const float* bp = Bs + (wn + ni * 8 + gid) * AST + k0 + tig;
                b[ni][0] = ldr(bp);
                b[ni][1] = ldr(bp + 4);
            }
#pragma unroll
            for (int mi = 0; mi < 4; mi++)
#pragma unroll
                for (int ni = 0; ni < 8; ni++)
                    mma_tf32_16x8x8(acc[mi][ni], a[mi], b[ni]);
        }
        __syncthreads();
    }

#pragma unroll
    for (int mi = 0; mi < 4; mi++) {
#pragma unroll
        for (int half = 0; half < 2; half++) {
            const int m = row0 + wm + mi * 16 + gid + half * 8;
            float* crow = C + (size_t)m * ldc + col0 + wn;
#pragma unroll
            for (int ni = 0; ni < 8; ni++) {
                const int cc = ni * 8 + 2 * tig;
                float2 v;
                v.x = acc[mi][ni][half * 2 + 0];
                v.y = acc[mi][ni][half * 2 + 1];
                if (bias) {
                    v.x += bias[col0 + wn + cc + 0];
                    v.y += bias[col0 + wn + cc + 1];
                }
                if (roundC) { v.x = rna_tf32(v.x); v.y = rna_tf32(v.y); }
                *(float2*)(crow + cc) = v;
            }
        }
    }
}

// ---------------------------------------------------------------------------
// Fused flash attention, tf32 mma.sync. CTA: 128 queries of one (b,h).
// K/V read from combined KV buffer (stride LDKV_, V at col offset 512).
// K/Q smem pad 68 (row-major conflict-free); V pad 72 (transposed conflict-free).
// ---------------------------------------------------------------------------
__global__ __launch_bounds__(256, 2) void flash_k(
    const float* __restrict__ Q, const float* __restrict__ KV,
    float* __restrict__ O)
{
    constexpr int PADK = 68, PADV = 72;
    constexpr int K_WORDS = 64 * PADK;     // one K stage
    constexpr int V_WORDS = 64 * PADV;     // one V stage
    extern __shared__ float sm[];
    const uint32_t sb = smem_u32(sm);

    const int tid = threadIdx.x, wid = tid >> 5, lane = tid & 31;
    const int gid = lane >> 2, tig = lane & 3;
    const int b = blockIdx.z, h = blockIdx.y, q0 = blockIdx.x * 128;
    const int wrow = wid * 16;

    const float* Qg = Q + ((size_t)(b * N_ + q0)) * INNER_ + h * DH_;
    const float* Kg = KV + ((size_t)b * M_) * LDKV_ + h * DH_;
    const float* Vg = Kg + INNER_;
    float*       Og = O + ((size_t)(b * N_ + q0)) * INNER_ + h * DH_;

    float* Ksm = sm;                              // [2][64][PADK]
    float* Vsm = sm + 2 * K_WORDS;                // [2][64][PADV]
    float* QP  = sm + 2 * K_WORDS + 2 * V_WORDS;  // [128][PADK]

    const uint32_t qp_base = sb + (uint32_t)((2 * K_WORDS + 2 * V_WORDS) * 4);
    const uint32_t v_base  = sb + (uint32_t)(2 * K_WORDS * 4);

    const int lr = tid >> 4, lch = tid & 15;

#pragma unroll
    for (int i = 0; i < 8; i++) {
        const int row = i * 16 + lr;
        cp16(qp_base + (uint32_t)((row * PADK + lch * 4) * 4),
             Qg + (size_t)row * INNER_ + lch * 4);
    }
    asm volatile("cp.async.commit_group;" ::: "memory");
    asm volatile("cp.async.wait_group 0;" ::: "memory");
    __syncthreads();

    uint32_t aq[8][4];
#pragma unroll
    for (int kq = 0; kq < 8; kq++) {
        const float* qp = QP + (wrow + gid) * PADK + kq * 8 + tig;
        aq[kq][0] = __float_as_uint(qp[0]);
        aq[kq][1] = __float_as_uint(qp[8 * PADK]);
        aq[kq][2] = __float_as_uint(qp[4]);
        aq[kq][3] = __float_as_uint(qp[8 * PADK + 4]);
    }

    float oacc[8][4];
#pragma unroll
    for (int ni = 0; ni < 8; ni++)
#pragma unroll
        for (int j = 0; j < 4; j++) oacc[ni][j] = 0.f;
    float m0 = -1e30f, m1 = -1e30f, l0 = 0.f, l1 = 0.f;

    auto prefetch = [&](int t, int s) {
#pragma unroll
        for (int q = 0; q < 4; q++) {
            const int row = q * 16 + lr;
            const size_t go = (size_t)(t * 64 + row) * LDKV_ + lch * 4;
            cp16(sb + (uint32_t)(((s * 64 + row) * PADK + lch * 4) * 4), Kg + go);
            cp16(v_base + (uint32_t)(((s * 64 + row) * PADV + lch * 4) * 4), Vg + go);
        }
        asm volatile("cp.async.commit_group;" ::: "memory");
    };
    prefetch(0, 0);

    for (int t = 0; t < M_ / 64; t++) {
        const int s = t & 1;
        if (t + 1 < M_ / 64) {
            prefetch(t + 1, s ^ 1);
            asm volatile("cp.async.wait_group 1;" ::: "memory");
        } else {
            asm volatile("cp.async.wait_group 0;" ::: "memory");
        }
        __syncthreads();

        const float* Ks = Ksm + s * K_WORDS;
        const float* Vs = Vsm + s * V_WORDS;

        float sacc[8][4];
#pragma unroll
        for (int ni = 0; ni < 8; ni++)
#pragma unroll
            for (int j = 0; j < 4; j++) sacc[ni][j] = 0.f;
#pragma unroll
        for (int kq = 0; kq < 8; kq++) {
#pragma unroll
            for (int ni = 0; ni < 8; ni++) {
                const float* kp = Ks + (ni * 8 + gid) * PADK + kq * 8 + tig;
                uint32_t bb[2] = { __float_as_uint(kp[0]), __float_as_uint(kp[4]) };
                mma_tf32_16x8x8(sacc[ni], aq[kq], bb);
            }
        }

        float r0m = -1e30f, r1m = -1e30f;
#pragma unroll
        for (int ni = 0; ni < 8; ni++) {
#pragma unroll
            for (int j = 0; j < 4; j++) sacc[ni][j] *= SCALE_;
            r0m = fmaxf(r0m, fmaxf(sacc[ni][0], sacc[ni][1]));
            r1m = fmaxf(r1m, fmaxf(sacc[ni][2], sacc[ni][3]));
        }
        r0m = fmaxf(r0m, __shfl_xor_sync(~0u, r0m, 1));
        r0m = fmaxf(r0m, __shfl_xor_sync(~0u, r0m, 2));
        r1m = fmaxf(r1m, __shfl_xor_sync(~0u, r1m, 1));
        r1m = fmaxf(r1m, __shfl_xor_sync(~0u, r1m, 2));
        const float nm0 = fmaxf(m0, r0m), nm1 = fmaxf(m1, r1m);
        const float c0 = __expf(m0 - nm0), c1 = __expf(m1 - nm1);
        float s0 = 0.f, s1 = 0.f;
        float* Pw = QP + wrow * PADK;
#pragma unroll
        for (int ni = 0; ni < 8; ni++) {
            const float p0 = __expf(sacc[ni][0] - nm0);
            const float p1 = __expf(sacc[ni][1] - nm0);
            const float p2 = __expf(sacc[ni][2] - nm1);
            const float p3 = __expf(sacc[ni][3] - nm1);
            s0 += p0 + p1; s1 += p2 + p3;
            float2 v0 = make_float2(rna_tf32(p0), rna_tf32(p1));
            float2 v1 = make_float2(rna_tf32(p2), rna_tf32(p3));
            *(float2*)(Pw + gid * PADK + ni * 8 + 2 * tig) = v0;
            *(float2*)(Pw + (gid + 8) * PADK + ni * 8 + 2 * tig) = v1;
        }
        s0 += __shfl_xor_sync(~0u, s0, 1); s0 += __shfl_xor_sync(~0u, s0, 2);
        s1 += __shfl_xor_sync(~0u, s1, 1); s1 += __shfl_xor_sync(~0u, s1, 2);
        l0 = l0 * c0 + s0; l1 = l1 * c1 + s1;
        m0 = nm0; m1 = nm1;
#pragma unroll
        for (int ni = 0; ni < 8; ni++) {
            oacc[ni][0] *= c0; oacc[ni][1] *= c0;
            oacc[ni][2] *= c1; oacc[ni][3] *= c1;
        }
        __syncwarp();

#pragma unroll
        for (int kq = 0; kq < 8; kq++) {
            const float* pp = Pw + gid * PADK + kq * 8 + tig;
            uint32_t ap[4] = {
                __float_as_uint(pp[0]), __float_as_uint(pp[8 * PADK]),
                __float_as_uint(pp[4]), __float_as_uint(pp[8 * PADK + 4]) };
#pragma unroll
            for (int ni = 0; ni < 8; ni++) {
                const float* vp = Vs + (kq * 8 + tig) * PADV + ni * 8 + gid;
                uint32_t bb[2] = { __float_as_uint(vp[0]),
                                   __float_as_uint(vp[4 * PADV]) };
                mma_tf32_16x8x8(oacc[ni], ap, bb);
            }
        }
        __syncwarp();
        __syncthreads();
    }

    const float inv0 = 1.f / l0, inv1 = 1.f / l1;
#pragma unroll
    for (int ni = 0; ni < 8; ni++) {
        const int cc = ni * 8 + 2 * tig;
        float2 v0 = make_float2(rna_tf32(oacc[ni][0] * inv0),
                                rna_tf32(oacc[ni][1] * inv0));
        float2 v1 = make_float2(rna_tf32(oacc[ni][2] * inv1),
                                rna_tf32(oacc[ni][3] * inv1));
        *(float2*)(Og + (size_t)(wrow + gid) * INNER_ + cc) = v0;
        *(float2*)(Og + (size_t)(wrow + gid + 8) * INNER_ + cc) = v1;
    }
}

// ---------------------------------------------------------------------------
// all 4 weight transposes in one launch (z selects weight), tf32-rounded
// ---------------------------------------------------------------------------
__global__ void transpose_all(
    const float* __restrict__ Wq, const float* __restrict__ Wk,
    const float* __restrict__ Wv, const float* __restrict__ Wo,
    float* __restrict__ WqT, float* __restrict__ WkvT, float* __restrict__ WoT)
{
    __shared__ float t[32][33];
    const int z = blockIdx.z;
    const float* in; float* out; int rows, cols;
    if      (z == 0) { in = Wq; out = WqT;  rows = 1024; cols = 512; }
    else if (z == 1) { in = Wk; out = WkvT; rows = 768;  cols = 512; }
    else if (z == 2) { in = Wv; out = WkvT + (size_t)512 * 768; rows = 768; cols = 512; }
    else             { in = Wo; out = WoT;  rows = 512;  cols = 1024; }

    const int c0 = blockIdx.x * 32, r0 = blockIdx.y * 32;
    if (c0 >= cols || r0 >= rows) return;
    const int x = threadIdx.x, y = threadIdx.y;
    for (int i = y; i < 32; i += 8) {
        int r = r0 + i, c = c0 + x;
        t[i][x] = (r < rows && c < cols) ? in[(size_t)r * cols + c] : 0.f;
    }
    __syncthreads();
    for (int i = y; i < 32; i += 8) {
        int orow = c0 + i, oc = r0 + x;
        if (orow < cols && oc < rows)
            out[(size_t)orow * rows + oc] = rna_tf32(t[x][i]);
    }
}

// ---------------------------------------------------------------------------
extern "C" void kernel_launch(void* const* d_in, const int* in_sizes, int n_in,
                              void* d_out, int out_size)
{
    const float* x   = (const float*)d_in[0];
    const float* ctx = (const float*)d_in[1];
    const float* Wq  = (const float*)d_in[2];
    const float* Wk  = (const float*)d_in[3];
    const float* Wv  = (const float*)d_in[4];
    const float* Wo  = (const float*)d_in[5];
    const float* bo  = (const float*)d_in[6];
    float* out = (float*)d_out;

    float *WqT, *WkvT, *WoT, *Q, *KV, *O;
    cudaGetSymbolAddress((void**)&WqT,  g_WqT);
    cudaGetSymbolAddress((void**)&WkvT, g_WkvT);
    cudaGetSymbolAddress((void**)&WoT,  g_WoT);
    cudaGetSymbolAddress((void**)&Q,    g_Q);
    cudaGetSymbolAddress((void**)&KV,   g_KV);
    cudaGetSymbolAddress((void**)&O,    g_O);

    const int SMEM_G = 2 * (128 + 128) * 36 * 4;                  // 73728 B
    const int SMEM_F = (2 * 64 * 68 + 2 * 64 * 72 + 128 * 68) * 4; // 106496 B
    cudaFuncSetAttribute(gemm_mma, cudaFuncAttributeMaxDynamicSharedMemorySize, SMEM_G);
    cudaFuncSetAttribute(flash_k,  cudaFuncAttributeMaxDynamicSharedMemorySize, SMEM_F);

    // 1) weight transposes (tf32-rounded), one launch
    transpose_all<<<dim3(32, 32, 4), dim3(32, 8)>>>(Wq, Wk, Wv, Wo, WqT, WkvT, WoT);

    // 2) projections
    gemm_mma<<<dim3(4, 128), 128, SMEM_G>>>(x,   WqT,  Q,  nullptr, 1024, 1024, 1024, 512, 1);
    gemm_mma<<<dim3(8, 32),  128, SMEM_G>>>(ctx, WkvT, KV, nullptr,  768,  768,  768, LDKV_, 1);

    // 3) fused flash attention -> O (rounded)
    flash_k<<<dim3(N_ / 128, H_, B_), 256, SMEM_F>>>(Q, KV, O);

    // 4) out = O Wo + bo
    gemm_mma<<<dim3(8, 128), 128, SMEM_G>>>(O, WoT, out, bo, 512, 512, 512, 1024, 0);
}

// round 8
// speedup vs baseline: 6.5455x; 1.0224x over previous
#include <cuda_runtime.h>
#include <cstdint>
#include <math.h>

#define B_     4
#define N_     4096
#define M_     1024
#define QD_    1024
#define CD_    768
#define H_     8
#define DH_    64
#define INNER_ 512
#define SCALE_ 0.125f
#define LDKV_  1024

// ---------------- scratch (__device__ globals; no allocation allowed) -------
__device__ float g_WqT [(size_t)INNER_ * QD_];
__device__ float g_WkvT[(size_t)2 * INNER_ * CD_];   // rows 0-511: WkT, 512-1023: WvT
__device__ float g_WoT [(size_t)QD_ * INNER_];
__device__ float g_Q   [(size_t)B_ * N_ * INNER_];
__device__ float g_KV  [(size_t)B_ * M_ * LDKV_];    // cols 0-511: K, 512-1023: V
__device__ float g_O   [(size_t)B_ * N_ * INNER_];

// ---------------- helpers ---------------------------------------------------
__device__ __forceinline__ uint32_t smem_u32(const void* p) {
    uint32_t a;
    asm("{ .reg .u64 t; cvta.to.shared.u64 t, %1; cvt.u32.u64 %0, t; }"
        : "=r"(a) : "l"(p));
    return a;
}
__device__ __forceinline__ float rna_tf32(float x) {
    float r; asm("cvt.rna.tf32.f32 %0, %1;" : "=f"(r) : "f"(x)); return r;
}
__device__ __forceinline__ uint32_t ldr(const float* p) {
    return __float_as_uint(rna_tf32(*p));
}
__device__ __forceinline__ void cp16(uint32_t dst, const void* src) {
    asm volatile("cp.async.cg.shared.global [%0], [%1], 16;"
                 :: "r"(dst), "l"(src) : "memory");
}
__device__ __forceinline__ void mma_tf32_16x8x8(
    float* c, const uint32_t* a, const uint32_t* b) {
    asm volatile(
        "mma.sync.aligned.m16n8k8.row.col.f32.tf32.tf32.f32 "
        "{%0,%1,%2,%3}, {%4,%5,%6,%7}, {%8,%9}, {%0,%1,%2,%3};"
        : "+f"(c[0]), "+f"(c[1]), "+f"(c[2]), "+f"(c[3])
        : "r"(a[0]), "r"(a[1]), "r"(a[2]), "r"(a[3]),
          "r"(b[0]), "r"(b[1]));
}

// ---------------------------------------------------------------------------
// GEMM body: C[M,N] tile (row0,col0) = A[M,K] * Bt[N,K]^T  (+bias, opt round)
// CTA tile 128x128x32, 128 threads = 4 warps, warp tile 64x64.
// ---------------------------------------------------------------------------
__device__ __forceinline__ void gemm_body(
    const float* __restrict__ A, const float* __restrict__ Bt,
    float* __restrict__ C, const float* __restrict__ bias,
    int K, int lda, int ldb, int ldc, int roundC,
    int row0, int col0, float* sm)
{
    constexpr int BM = 128, BN = 128;
    constexpr int AST = 36;
    constexpr int A_WORDS = BM * AST;
    constexpr int STAGE_WORDS = (BM + BN) * AST;

    const uint32_t sb = smem_u32(sm);
    const int tid = threadIdx.x, wid = tid >> 5, lane = tid & 31;
    const int gid = lane >> 2, tig = lane & 3;
    const int wm = (wid & 1) * 64, wn = (wid >> 1) * 64;

    const int lr = tid >> 3;
    const int lh = tid & 7;
    const float* Ag = A + (size_t)(row0 + lr) * lda + lh * 4;
    const float* Bg = Bt + (size_t)(col0 + lr) * ldb + lh * 4;
    const uint32_t aoff = (uint32_t)((lr * AST + lh * 4) * 4);
    const uint32_t boff = (uint32_t)((A_WORDS + lr * AST + lh * 4) * 4);

    float acc[4][8][4];
#pragma unroll
    for (int mi = 0; mi < 4; mi++)
#pragma unroll
        for (int ni = 0; ni < 8; ni++)
#pragma unroll
            for (int j = 0; j < 4; j++) acc[mi][ni][j] = 0.f;

    const int nt = K >> 5;
    {
#pragma unroll
        for (int q = 0; q < 8; q++) {
            cp16(sb + aoff + (uint32_t)(q * 16 * AST * 4), Ag + (size_t)q * 16 * lda);
            cp16(sb + boff + (uint32_t)(q * 16 * AST * 4), Bg + (size_t)q * 16 * ldb);
        }
        asm volatile("cp.async.commit_group;" ::: "memory");
    }

    for (int kt = 0; kt < nt; kt++) {
        const int s = kt & 1;
        if (kt + 1 < nt) {
            const uint32_t st = sb + (uint32_t)((s ^ 1) * STAGE_WORDS) * 4u;
            const size_t ko = (size_t)(kt + 1) * 32;
#pragma unroll
            for (int q = 0; q < 8; q++) {
                cp16(st + aoff + (uint32_t)(q * 16 * AST * 4),
                     Ag + (size_t)q * 16 * lda + ko);
                cp16(st + boff + (uint32_t)(q * 16 * AST * 4),
                     Bg + (size_t)q * 16 * ldb + ko);
            }
            asm volatile("cp.async.commit_group;" ::: "memory");
            asm volatile("cp.async.wait_group 1;" ::: "memory");
        } else {
            asm volatile("cp.async.wait_group 0;" ::: "memory");
        }
        __syncthreads();

        const float* As = sm + s * STAGE_WORDS;
        const float* Bs = As + A_WORDS;
#pragma unroll
        for (int kq = 0; kq < 4; kq++) {
            const int k0 = kq * 8;
            uint32_t a[4][4], b[8][2];
#pragma unroll
            for (int mi = 0; mi < 4; mi++) {
                const float* ap = As + (wm + mi * 16 + gid) * AST + k0 + tig;
                a[mi][0] = ldr(ap);
                a[mi][1] = ldr(ap + 8 * AST);
                a[mi][2] = ldr(ap + 4);
                a[mi][3] = ldr(ap + 8 * AST + 4);
            }
#pragma unroll
            for (int ni = 0; ni < 8; ni++) {
                const float* bp = Bs + (wn + ni * 8 + gid) * AST + k0 + tig;
                b[ni][0] = ldr(bp);
                b[ni][1] = ldr(bp + 4);
            }
#pragma unroll
            for (int mi = 0; mi < 4; mi++)
#pragma unroll
                for (int ni = 0; ni < 8; ni++)
                    mma_tf32_16x8x8(acc[mi][ni], a[mi], b[ni]);
        }
        __syncthreads();
    }

#pragma unroll
    for (int mi = 0; mi < 4; mi++) {
#pragma unroll
        for (int half = 0; half < 2; half++) {
            const int m = row0 + wm + mi * 16 + gid + half * 8;
            float* crow = C + (size_t)m * ldc + col0 + wn;
#pragma unroll
            for (int ni = 0; ni < 8; ni++) {
                const int cc = ni * 8 + 2 * tig;
                float2 v;
                v.x = acc[mi][ni][half * 2 + 0];
                v.y = acc[mi][ni][half * 2 + 1];
                if (bias) {
                    v.x += bias[col0 + wn + cc + 0];
                    v.y += bias[col0 + wn + cc + 1];
                }
                if (roundC) { v.x = rna_tf32(v.x); v.y = rna_tf32(v.y); }
                *(float2*)(crow + cc) = v;
            }
        }
    }
}

// generic GEMM (used for out-proj)
__global__ __launch_bounds__(128, 3) void gemm_mma(
    const float* __restrict__ A, const float* __restrict__ Bt,
    float* __restrict__ C, const float* __restrict__ bias,
    int K, int lda, int ldb, int ldc, int roundC)
{
    extern __shared__ float sm[];
    gemm_body(A, Bt, C, bias, K, lda, ldb, ldc, roundC,
              blockIdx.y * 128, blockIdx.x * 128, sm);
}

// merged Q-proj (512 CTAs) + KV-proj (256 CTAs) in one 768-CTA launch
__global__ __launch_bounds__(128, 3) void qkv_proj(
    const float* __restrict__ x,   const float* __restrict__ WqT,
    float* __restrict__ Q,
    const float* __restrict__ ctx, const float* __restrict__ WkvT,
    float* __restrict__ KV)
{
    extern __shared__ float sm[];
    const int idx = blockIdx.x;
    if (idx < 512) {
        gemm_body(x, WqT, Q, nullptr, 1024, 1024, 1024, 512, 1,
                  (idx >> 2) * 128, (idx & 3) * 128, sm);
    } else {
        const int j = idx - 512;
        gemm_body(ctx, WkvT, KV, nullptr, 768, 768, 768, LDKV_, 1,
                  (j >> 3) * 128, (j & 7) * 128, sm);
    }
}

// ---------------------------------------------------------------------------
// Fused flash attention, tf32 mma.sync. CTA: 128 queries of one (b,h).
// P kept in registers: accumulator->A-fragment layout conversion via shfl
// (no smem round-trip). Q staged through the K stage buffers at startup.
// ---------------------------------------------------------------------------
__global__ __launch_bounds__(256, 2) void flash_k(
    const float* __restrict__ Q, const float* __restrict__ KV,
    float* __restrict__ O)
{
    constexpr int PADK = 68, PADV = 72;
    constexpr int K_WORDS = 64 * PADK;
    constexpr int V_WORDS = 64 * PADV;
    extern __shared__ float sm[];
    const uint32_t sb = smem_u32(sm);

    const int tid = threadIdx.x, wid = tid >> 5, lane = tid & 31;
    const int gid = lane >> 2, tig = lane & 3;
    const int b = blockIdx.z, h = blockIdx.y, q0 = blockIdx.x * 128;
    const int wrow = wid * 16;

    const float* Qg = Q + ((size_t)(b * N_ + q0)) * INNER_ + h * DH_;
    const float* Kg = KV + ((size_t)b * M_) * LDKV_ + h * DH_;
    const float* Vg = Kg + INNER_;
    float*       Og = O + ((size_t)(b * N_ + q0)) * INNER_ + h * DH_;

    float* Ksm = sm;                    // [2][64][PADK]; also Q staging at start
    float* Vsm = sm + 2 * K_WORDS;      // [2][64][PADV]
    const uint32_t v_base = sb + (uint32_t)(2 * K_WORDS * 4);

    const int lr = tid >> 4, lch = tid & 15;

    // ---- stage Q tile into the K stage area (128 rows x PADK) ----
#pragma unroll
    for (int i = 0; i < 8; i++) {
        const int row = i * 16 + lr;
        cp16(sb + (uint32_t)((row * PADK + lch * 4) * 4),
             Qg + (size_t)row * INNER_ + lch * 4);
    }
    asm volatile("cp.async.commit_group;" ::: "memory");
    asm volatile("cp.async.wait_group 0;" ::: "memory");
    __syncthreads();

    uint32_t aq[8][4];
#pragma unroll
    for (int kq = 0; kq < 8; kq++) {
        const float* qp = Ksm + (wrow + gid) * PADK + kq * 8 + tig;
        aq[kq][0] = __float_as_uint(qp[0]);
        aq[kq][1] = __float_as_uint(qp[8 * PADK]);
        aq[kq][2] = __float_as_uint(qp[4]);
        aq[kq][3] = __float_as_uint(qp[8 * PADK + 4]);
    }
    __syncthreads();   // all aq loaded before K prefetch overwrites the area

    float oacc[8][4];
#pragma unroll
    for (int ni = 0; ni < 8; ni++)
#pragma unroll
        for (int j = 0; j < 4; j++) oacc[ni][j] = 0.f;
    float m0 = -1e30f, m1 = -1e30f, l0 = 0.f, l1 = 0.f;

    auto prefetch = [&](int t, int s) {
#pragma unroll
        for (int q = 0; q < 4; q++) {
            const int row = q * 16 + lr;
            const size_t go = (size_t)(t * 64 + row) * LDKV_ + lch * 4;
            cp16(sb + (uint32_t)(((s * 64 + row) * PADK + lch * 4) * 4), Kg + go);
            cp16(v_base + (uint32_t)(((s * 64 + row) * PADV + lch * 4) * 4), Vg + go);
        }
        asm volatile("cp.async.commit_group;" ::: "memory");
    };
    prefetch(0, 0);

    // shuffle source lanes for accumulator->A-fragment conversion
    const int L1 = (gid << 2) | (tig >> 1);
    const int L2 = L1 + 2;
    const bool e = (tig & 1);

    for (int t = 0; t < M_ / 64; t++) {
        const int s = t & 1;
        if (t + 1 < M_ / 64) {
            prefetch(t + 1, s ^ 1);
            asm volatile("cp.async.wait_group 1;" ::: "memory");
        } else {
            asm volatile("cp.async.wait_group 0;" ::: "memory");
        }
        __syncthreads();

        const float* Ks = Ksm + s * K_WORDS;
        const float* Vs = Vsm + s * V_WORDS;

        // ---- S = Q K^T ----
        float sacc[8][4];
#pragma unroll
        for (int ni = 0; ni < 8; ni++)
#pragma unroll
            for (int j = 0; j < 4; j++) sacc[ni][j] = 0.f;
#pragma unroll
        for (int kq = 0; kq < 8; kq++) {
#pragma unroll
            for (int ni = 0; ni < 8; ni++) {
                const float* kp = Ks + (ni * 8 + gid) * PADK + kq * 8 + tig;
                uint32_t bb[2] = { __float_as_uint(kp[0]), __float_as_uint(kp[4]) };
                mma_tf32_16x8x8(sacc[ni], aq[kq], bb);
            }
        }

        // ---- online softmax ----
        float r0m = -1e30f, r1m = -1e30f;
#pragma unroll
        for (int ni = 0; ni < 8; ni++) {
#pragma unroll
            for (int j = 0; j < 4; j++) sacc[ni][j] *= SCALE_;
            r0m = fmaxf(r0m, fmaxf(sacc[ni][0], sacc[ni][1]));
            r1m = fmaxf(r1m, fmaxf(sacc[ni][2], sacc[ni][3]));
        }
        r0m = fmaxf(r0m, __shfl_xor_sync(~0u, r0m, 1));
        r0m = fmaxf(r0m, __shfl_xor_sync(~0u, r0m, 2));
        r1m = fmaxf(r1m, __shfl_xor_sync(~0u, r1m, 1));
        r1m = fmaxf(r1m, __shfl_xor_sync(~0u, r1m, 2));
        const float nm0 = fmaxf(m0, r0m), nm1 = fmaxf(m1, r1m);
        const float c0 = __expf(m0 - nm0), c1 = __expf(m1 - nm1);
        float s0 = 0.f, s1 = 0.f;

        // P fragments in registers via shfl (accumulator -> A-fragment layout)
        uint32_t pa[8][4];
#pragma unroll
        for (int ni = 0; ni < 8; ni++) {
            const float p0r = __expf(sacc[ni][0] - nm0);
            const float p1r = __expf(sacc[ni][1] - nm0);
            const float p2r = __expf(sacc[ni][2] - nm1);
            const float p3r = __expf(sacc[ni][3] - nm1);
            s0 += p0r + p1r; s1 += p2r + p3r;
            const float q0 = rna_tf32(p0r), q1 = rna_tf32(p1r);
            const float q2 = rna_tf32(p2r), q3 = rna_tf32(p3r);
            const float u0a = __shfl_sync(~0u, q0, L1);
            const float u1a = __shfl_sync(~0u, q1, L1);
            const float u2a = __shfl_sync(~0u, q2, L1);
            const float u3a = __shfl_sync(~0u, q3, L1);
            const float u0b = __shfl_sync(~0u, q0, L2);
            const float u1b = __shfl_sync(~0u, q1, L2);
            const float u2b = __shfl_sync(~0u, q2, L2);
            const float u3b = __shfl_sync(~0u, q3, L2);
            pa[ni][0] = __float_as_uint(e ? u1a : u0a);   // (gid,   tig)
            pa[ni][1] = __float_as_uint(e ? u3a : u2a);   // (gid+8, tig)
            pa[ni][2] = __float_as_uint(e ? u1b : u0b);   // (gid,   tig+4)
            pa[ni][3] = __float_as_uint(e ? u3b : u2b);   // (gid+8, tig+4)
        }
        s0 += __shfl_xor_sync(~0u, s0, 1); s0 += __shfl_xor_sync(~0u, s0, 2);
        s1 += __shfl_xor_sync(~0u, s1, 1); s1 += __shfl_xor_sync(~0u, s1, 2);
        l0 = l0 * c0 + s0; l1 = l1 * c1 + s1;
        m0 = nm0; m1 = nm1;
#pragma unroll
        for (int ni = 0; ni < 8; ni++) {
            oacc[ni][0] *= c0; oacc[ni][1] *= c0;
            oacc[ni][2] *= c1; oacc[ni][3] *= c1;
        }

        // ---- O += P V ----
#pragma unroll
        for (int kq = 0; kq < 8; kq++) {
#pragma unroll
            for (int ni = 0; ni < 8; ni++) {
                const float* vp = Vs + (kq * 8 + tig) * PADV + ni * 8 + gid;
                uint32_t bb[2] = { __float_as_uint(vp[0]),
                                   __float_as_uint(vp[4 * PADV]) };
                mma_tf32_16x8x8(oacc[ni], pa[kq], bb);
            }
        }
        __syncthreads();
    }

    const float inv0 = 1.f / l0, inv1 = 1.f / l1;
#pragma unroll
    for (int ni = 0; ni < 8; ni++) {
        const int cc = ni * 8 + 2 * tig;
        float2 v0 = make_float2(rna_tf32(oacc[ni][0] * inv0),
                                rna_tf32(oacc[ni][1] * inv0));
        float2 v1 = make_float2(rna_tf32(oacc[ni][2] * inv1),
                                rna_tf32(oacc[ni][3] * inv1));
        *(float2*)(Og + (size_t)(wrow + gid) * INNER_ + cc) = v0;
        *(float2*)(Og + (size_t)(wrow + gid + 8) * INNER_ + cc) = v1;
    }
}

// ---------------------------------------------------------------------------
// all 4 weight transposes in one launch (z selects weight), tf32-rounded
// ---------------------------------------------------------------------------
__global__ void transpose_all(
    const float* __restrict__ Wq, const float* __restrict__ Wk,
    const float* __restrict__ Wv, const float* __restrict__ Wo,
    float* __restrict__ WqT, float* __restrict__ WkvT, float* __restrict__ WoT)
{
    __shared__ float t[32][33];
    const int z = blockIdx.z;
    const float* in; float* out; int rows, cols;
    if      (z == 0) { in = Wq; out = WqT;  rows = 1024; cols = 512; }
    else if (z == 1) { in = Wk; out = WkvT; rows = 768;  cols = 512; }
    else if (z == 2) { in = Wv; out = WkvT + (size_t)512 * 768; rows = 768; cols = 512; }
    else             { in = Wo; out = WoT;  rows = 512;  cols = 1024; }

    const int c0 = blockIdx.x * 32, r0 = blockIdx.y * 32;
    if (c0 >= cols || r0 >= rows) return;
    const int x = threadIdx.x, y = threadIdx.y;
    for (int i = y; i < 32; i += 8) {
        int r = r0 + i, c = c0 + x;
        t[i][x] = (r < rows && c < cols) ? in[(size_t)r * cols + c] : 0.f;
    }
    __syncthreads();
    for (int i = y; i < 32; i += 8) {
        int orow = c0 + i, oc = r0 + x;
        if (orow < cols && oc < rows)
            out[(size_t)orow * rows + oc] = rna_tf32(t[x][i]);
    }
}

// ---------------------------------------------------------------------------
extern "C" void kernel_launch(void* const* d_in, const int* in_sizes, int n_in,
                              void* d_out, int out_size)
{
    const float* x   = (const float*)d_in[0];
    const float* ctx = (const float*)d_in[1];
    const float* Wq  = (const float*)d_in[2];
    const float* Wk  = (const float*)d_in[3];
    const float* Wv  = (const float*)d_in[4];
    const float* Wo  = (const float*)d_in[5];
    const float* bo  = (const float*)d_in[6];
    float* out = (float*)d_out;

    float *WqT, *WkvT, *WoT, *Q, *KV, *O;
    cudaGetSymbolAddress((void**)&WqT,  g_WqT);
    cudaGetSymbolAddress((void**)&WkvT, g_WkvT);
    cudaGetSymbolAddress((void**)&WoT,  g_WoT);
    cudaGetSymbolAddress((void**)&Q,    g_Q);
    cudaGetSymbolAddress((void**)&KV,   g_KV);
    cudaGetSymbolAddress((void**)&O,    g_O);

    const int SMEM_G = 2 * (128 + 128) * 36 * 4;           // 73728 B
    const int SMEM_F = (2 * 64 * 68 + 2 * 64 * 72) * 4;    // 71680 B
    cudaFuncSetAttribute(gemm_mma, cudaFuncAttributeMaxDynamicSharedMemorySize, SMEM_G);
    cudaFuncSetAttribute(qkv_proj, cudaFuncAttributeMaxDynamicSharedMemorySize, SMEM_G);
    cudaFuncSetAttribute(flash_k,  cudaFuncAttributeMaxDynamicSharedMemorySize, SMEM_F);

    // 1) weight transposes (tf32-rounded), one launch
    transpose_all<<<dim3(32, 32, 4), dim3(32, 8)>>>(Wq, Wk, Wv, Wo, WqT, WkvT, WoT);

    // 2) merged Q + KV projections (wave-filling)
    qkv_proj<<<768, 128, SMEM_G>>>(x, WqT, Q, ctx, WkvT, KV);

    // 3) fused flash attention -> O (rounded)
    flash_k<<<dim3(N_ / 128, H_, B_), 256, SMEM_F>>>(Q, KV, O);

    // 4) out = O Wo + bo
    gemm_mma<<<dim3(8, 128), 128, SMEM_G>>>(O, WoT, out, bo, 512, 512, 512, 1024, 0);
}

// round 9
// speedup vs baseline: 6.9344x; 1.0594x over previous
#include <cuda_runtime.h>
#include <cstdint>
#include <math.h>

#define B_     4
#define N_     4096
#define M_     1024
#define QD_    1024
#define CD_    768
#define H_     8
#define DH_    64
#define INNER_ 512
#define SCALE_ 0.125f
#define LDKV_  1024

// ---------------- scratch (__device__ globals; no allocation allowed) -------
__device__ float g_WqT [(size_t)INNER_ * QD_];
__device__ float g_WkvT[(size_t)2 * INNER_ * CD_];   // rows 0-511: WkT, 512-1023: WvT
__device__ float g_WoT [(size_t)QD_ * INNER_];
__device__ float g_Q   [(size_t)B_ * N_ * INNER_];
__device__ float g_KV  [(size_t)B_ * M_ * LDKV_];    // cols 0-511: K, 512-1023: V
__device__ float g_O   [(size_t)B_ * N_ * INNER_];

// ---------------- helpers ---------------------------------------------------
__device__ __forceinline__ uint32_t smem_u32(const void* p) {
    uint32_t a;
    asm("{ .reg .u64 t; cvta.to.shared.u64 t, %1; cvt.u32.u64 %0, t; }"
        : "=r"(a) : "l"(p));
    return a;
}
__device__ __forceinline__ float rna_tf32(float x) {
    float r; asm("cvt.rna.tf32.f32 %0, %1;" : "=f"(r) : "f"(x)); return r;
}
template <int RND>
__device__ __forceinline__ uint32_t ldf(const float* p) {
    return RND ? __float_as_uint(rna_tf32(*p)) : __float_as_uint(*p);
}
__device__ __forceinline__ void cp16(uint32_t dst, const void* src) {
    asm volatile("cp.async.cg.shared.global [%0], [%1], 16;"
                 :: "r"(dst), "l"(src) : "memory");
}
__device__ __forceinline__ void mma_tf32_16x8x8(
    float* c, const uint32_t* a, const uint32_t* b) {
    asm volatile(
        "mma.sync.aligned.m16n8k8.row.col.f32.tf32.tf32.f32 "
        "{%0,%1,%2,%3}, {%4,%5,%6,%7}, {%8,%9}, {%0,%1,%2,%3};"
        : "+f"(c[0]), "+f"(c[1]), "+f"(c[2]), "+f"(c[3])
        : "r"(a[0]), "r"(a[1]), "r"(a[2]), "r"(a[3]),
          "r"(b[0]), "r"(b[1]));
}

// ---------------------------------------------------------------------------
// GEMM body: C tile (row0,col0) = A[M,K] * Bt[N,K]^T  (+bias, opt round)
// CTA tile 128x128x32, 128 threads = 4 warps, warp tile 64x64.
// RA/RB: rna-round A/B fragments at register load (0 if operand pre-rounded).
// ---------------------------------------------------------------------------
template <int RA, int RB>
__device__ __forceinline__ void gemm_body(
    const float* __restrict__ A, const float* __restrict__ Bt,
    float* __restrict__ C, const float* __restrict__ bias,
    int K, int lda, int ldb, int ldc, int roundC,
    int row0, int col0, float* sm)
{
    constexpr int BM = 128, BN = 128;
    constexpr int AST = 36;
    constexpr int A_WORDS = BM * AST;
    constexpr int STAGE_WORDS = (BM + BN) * AST;

    const uint32_t sb = smem_u32(sm);
    const int tid = threadIdx.x, wid = tid >> 5, lane = tid & 31;
    const int gid = lane >> 2, tig = lane & 3;
    const int wm = (wid & 1) * 64, wn = (wid >> 1) * 64;

    const int lr = tid >> 3;
    const int lh = tid & 7;
    const float* Ag = A + (size_t)(row0 + lr) * lda + lh * 4;
    const float* Bg = Bt + (size_t)(col0 + lr) * ldb + lh * 4;
    const uint32_t aoff = (uint32_t)((lr * AST + lh * 4) * 4);
    const uint32_t boff = (uint32_t)((A_WORDS + lr * AST + lh * 4) * 4);

    float acc[4][8][4];
#pragma unroll
    for (int mi = 0; mi < 4; mi++)
#pragma unroll
        for (int ni = 0; ni < 8; ni++)
#pragma unroll
            for (int j = 0; j < 4; j++) acc[mi][ni][j] = 0.f;

    const int nt = K >> 5;
    {
#pragma unroll
        for (int q = 0; q < 8; q++) {
            cp16(sb + aoff + (uint32_t)(q * 16 * AST * 4), Ag + (size_t)q * 16 * lda);
            cp16(sb + boff + (uint32_t)(q * 16 * AST * 4), Bg + (size_t)q * 16 * ldb);
        }
        asm volatile("cp.async.commit_group;" ::: "memory");
    }

    for (int kt = 0; kt < nt; kt++) {
        const int s = kt & 1;
        if (kt + 1 < nt) {
            const uint32_t st = sb + (uint32_t)((s ^ 1) * STAGE_WORDS) * 4u;
            const size_t ko = (size_t)(kt + 1) * 32;
#pragma unroll
            for (int q = 0; q < 8; q++) {
                cp16(st + aoff + (uint32_t)(q * 16 * AST * 4),
                     Ag + (size_t)q * 16 * lda + ko);
                cp16(st + boff + (uint32_t)(q * 16 * AST * 4),
                     Bg + (size_t)q * 16 * ldb + ko);
            }
            asm volatile("cp.async.commit_group;" ::: "memory");
            asm volatile("cp.async.wait_group 1;" ::: "memory");
        } else {
            asm volatile("cp.async.wait_group 0;" ::: "memory");
        }
        __syncthreads();

        const float* As = sm + s * STAGE_WORDS;
        const float* Bs = As + A_WORDS;
#pragma unroll
        for (int kq = 0; kq < 4; kq++) {
            const int k0 = kq * 8;
            uint32_t a[4][4], b[8][2];
#pragma unroll
            for (int mi = 0; mi < 4; mi++) {
                const float* ap = As + (wm + mi * 16 + gid) * AST + k0 + tig;
                a[mi][0] = ldf<RA>(ap);
                a[mi][1] = ldf<RA>(ap + 8 * AST);
                a[mi][2] = ldf<RA>(ap + 4);
                a[mi][3] = ldf<RA>(ap + 8 * AST + 4);
            }
#pragma unroll
            for (int ni = 0; ni < 8; ni++) {
                const float* bp = Bs + (wn + ni * 8 + gid) * AST + k0 + tig;
                b[ni][0] = ldf<RB>(bp);
                b[ni][1] = ldf<RB>(bp + 4);
            }
#pragma unroll
            for (int mi = 0; mi < 4; mi++)
#pragma unroll
                for (int ni = 0; ni < 8; ni++)
                    mma_tf32_16x8x8(acc[mi][ni], a[mi], b[ni]);
        }
        __syncthreads();
    }

#pragma unroll
    for (int mi = 0; mi < 4; mi++) {
#pragma unroll
        for (int half = 0; half < 2; half++) {
            const int m = row0 + wm + mi * 16 + gid + half * 8;
            float* crow = C + (size_t)m * ldc + col0 + wn;
#pragma unroll
            for (int ni = 0; ni < 8; ni++) {
                const int cc = ni * 8 + 2 * tig;
                float2 v;
                v.x = acc[mi][ni][half * 2 + 0];
                v.y = acc[mi][ni][half * 2 + 1];
                if (bias) {
                    v.x += bias[col0 + wn + cc + 0];
                    v.y += bias[col0 + wn + cc + 1];
                }
                if (roundC) { v.x = rna_tf32(v.x); v.y = rna_tf32(v.y); }
                *(float2*)(crow + cc) = v;
            }
        }
    }
}

// out-proj: O (rounded) x WoT (rounded) -> no cvts at all
__global__ __launch_bounds__(128, 3) void gemm_oproj(
    const float* __restrict__ A, const float* __restrict__ Bt,
    float* __restrict__ C, const float* __restrict__ bias,
    int K, int lda, int ldb, int ldc)
{
    extern __shared__ float sm[];
    gemm_body<0, 0>(A, Bt, C, bias, K, lda, ldb, ldc, 0,
                    blockIdx.y * 128, blockIdx.x * 128, sm);
}

// merged Q-proj (512 CTAs) + KV-proj (256 CTAs); A raw (round), B pre-rounded
__global__ __launch_bounds__(128, 3) void qkv_proj(
    const float* __restrict__ x,   const float* __restrict__ WqT,
    float* __restrict__ Q,
    const float* __restrict__ ctx, const float* __restrict__ WkvT,
    float* __restrict__ KV)
{
    extern __shared__ float sm[];
    const int idx = blockIdx.x;
    if (idx < 512) {
        gemm_body<1, 0>(x, WqT, Q, nullptr, 1024, 1024, 1024, 512, 1,
                        (idx >> 2) * 128, (idx & 3) * 128, sm);
    } else {
        const int j = idx - 512;
        gemm_body<1, 0>(ctx, WkvT, KV, nullptr, 768, 768, 768, LDKV_, 1,
                        (j >> 3) * 128, (j & 7) * 128, sm);
    }
}

// ---------------------------------------------------------------------------
// Fused flash attention, tf32 mma.sync. CTA: 128 queries of one (b,h).
// 3-stage KV ring -> single __syncthreads per tile. P via register shuffles.
// ---------------------------------------------------------------------------
__global__ __launch_bounds__(256, 2) void flash_k(
    const float* __restrict__ Q, const float* __restrict__ KV,
    float* __restrict__ O)
{
    constexpr int PADK = 68, PADV = 72;
    constexpr int K_WORDS = 64 * PADK;
    constexpr int V_WORDS = 64 * PADV;
    constexpr int NT = M_ / 64;
    extern __shared__ float sm[];
    const uint32_t sb = smem_u32(sm);

    const int tid = threadIdx.x, wid = tid >> 5, lane = tid & 31;
    const int gid = lane >> 2, tig = lane & 3;
    const int b = blockIdx.z, h = blockIdx.y, q0 = blockIdx.x * 128;
    const int wrow = wid * 16;

    const float* Qg = Q + ((size_t)(b * N_ + q0)) * INNER_ + h * DH_;
    const float* Kg = KV + ((size_t)b * M_) * LDKV_ + h * DH_;
    const float* Vg = Kg + INNER_;
    float*       Og = O + ((size_t)(b * N_ + q0)) * INNER_ + h * DH_;

    float* Ksm = sm;                      // [3][64][PADK]; Q staging at start
    float* Vsm = sm + 3 * K_WORDS;        // [3][64][PADV]
    const uint32_t v_base = sb + (uint32_t)(3 * K_WORDS * 4);

    const int lr = tid >> 4, lch = tid & 15;

    // ---- stage Q tile into K ring (128 rows x PADK = first 2 stages) ----
#pragma unroll
    for (int i = 0; i < 8; i++) {
        const int row = i * 16 + lr;
        cp16(sb + (uint32_t)((row * PADK + lch * 4) * 4),
             Qg + (size_t)row * INNER_ + lch * 4);
    }
    asm volatile("cp.async.commit_group;" ::: "memory");
    asm volatile("cp.async.wait_group 0;" ::: "memory");
    __syncthreads();

    uint32_t aq[8][4];
#pragma unroll
    for (int kq = 0; kq < 8; kq++) {
        const float* qp = Ksm + (wrow + gid) * PADK + kq * 8 + tig;
        aq[kq][0] = __float_as_uint(qp[0]);
        aq[kq][1] = __float_as_uint(qp[8 * PADK]);
        aq[kq][2] = __float_as_uint(qp[4]);
        aq[kq][3] = __float_as_uint(qp[8 * PADK + 4]);
    }
    __syncthreads();   // aq loaded before KV prefetch overwrites the ring

    float oacc[8][4];
#pragma unroll
    for (int ni = 0; ni < 8; ni++)
#pragma unroll
        for (int j = 0; j < 4; j++) oacc[ni][j] = 0.f;
    float m0 = -1e30f, m1 = -1e30f, l0 = 0.f, l1 = 0.f;

    auto prefetch = [&](int t, int s) {
#pragma unroll
        for (int q = 0; q < 4; q++) {
            const int row = q * 16 + lr;
            const size_t go = (size_t)(t * 64 + row) * LDKV_ + lch * 4;
            cp16(sb + (uint32_t)(((s * 64 + row) * PADK + lch * 4) * 4), Kg + go);
            cp16(v_base + (uint32_t)(((s * 64 + row) * PADV + lch * 4) * 4), Vg + go);
        }
        asm volatile("cp.async.commit_group;" ::: "memory");
    };
    prefetch(0, 0);
    prefetch(1, 1);

    const int L1 = (gid << 2) | (tig >> 1);
    const int L2 = L1 + 2;
    const bool e = (tig & 1);

    for (int t = 0; t < NT; t++) {
        const int s = t % 3;
        if (t + 1 < NT) {
            asm volatile("cp.async.wait_group 1;" ::: "memory");
        } else {
            asm volatile("cp.async.wait_group 0;" ::: "memory");
        }
        __syncthreads();           // single barrier per tile
        if (t + 2 < NT) prefetch(t + 2, (t + 2) % 3);

        const float* Ks = Ksm + s * K_WORDS;
        const float* Vs = Vsm + s * V_WORDS;

        // ---- S = Q K^T ----
        float sacc[8][4];
#pragma unroll
        for (int ni = 0; ni < 8; ni++)
#pragma unroll
            for (int j = 0; j < 4; j++) sacc[ni][j] = 0.f;
#pragma unroll
        for (int kq = 0; kq < 8; kq++) {
#pragma unroll
            for (int ni = 0; ni < 8; ni++) {
                const float* kp = Ks + (ni * 8 + gid) * PADK + kq * 8 + tig;
                uint32_t bb[2] = { __float_as_uint(kp[0]), __float_as_uint(kp[4]) };
                mma_tf32_16x8x8(sacc[ni], aq[kq], bb);
            }
        }

        // ---- online softmax ----
        float r0m = -1e30f, r1m = -1e30f;
#pragma unroll
        for (int ni = 0; ni < 8; ni++) {
#pragma unroll
            for (int j = 0; j < 4; j++) sacc[ni][j] *= SCALE_;
            r0m = fmaxf(r0m, fmaxf(sacc[ni][0], sacc[ni][1]));
            r1m = fmaxf(r1m, fmaxf(sacc[ni][2], sacc[ni][3]));
        }
        r0m = fmaxf(r0m, __shfl_xor_sync(~0u, r0m, 1));
        r0m = fmaxf(r0m, __shfl_xor_sync(~0u, r0m, 2));
        r1m = fmaxf(r1m, __shfl_xor_sync(~0u, r1m, 1));
        r1m = fmaxf(r1m, __shfl_xor_sync(~0u, r1m, 2));
        const float nm0 = fmaxf(m0, r0m), nm1 = fmaxf(m1, r1m);
        const float c0 = __expf(m0 - nm0), c1 = __expf(m1 - nm1);
        float s0 = 0.f, s1 = 0.f;

        uint32_t pa[8][4];
#pragma unroll
        for (int ni = 0; ni < 8; ni++) {
            const float p0r = __expf(sacc[ni][0] - nm0);
            const float p1r = __expf(sacc[ni][1] - nm0);
            const float p2r = __expf(sacc[ni][2] - nm1);
            const float p3r = __expf(sacc[ni][3] - nm1);
            s0 += p0r + p1r; s1 += p2r + p3r;
            const float q0 = rna_tf32(p0r), q1 = rna_tf32(p1r);
            const float q2 = rna_tf32(p2r), q3 = rna_tf32(p3r);
            const float u0a = __shfl_sync(~0u, q0, L1);
            const float u1a = __shfl_sync(~0u, q1, L1);
            const float u2a = __shfl_sync(~0u, q2, L1);
            const float u3a = __shfl_sync(~0u, q3, L1);
            const float u0b = __shfl_sync(~0u, q0, L2);
            const float u1b = __shfl_sync(~0u, q1, L2);
            const float u2b = __shfl_sync(~0u, q2, L2);
            const float u3b = __shfl_sync(~0u, q3, L2);
            pa[ni][0] = __float_as_uint(e ? u1a : u0a);
            pa[ni][1] = __float_as_uint(e ? u3a : u2a);
            pa[ni][2] = __float_as_uint(e ? u1b : u0b);
            pa[ni][3] = __float_as_uint(e ? u3b : u2b);
        }
        s0 += __shfl_xor_sync(~0u, s0, 1); s0 += __shfl_xor_sync(~0u, s0, 2);
        s1 += __shfl_xor_sync(~0u, s1, 1); s1 += __shfl_xor_sync(~0u, s1, 2);
        l0 = l0 * c0 + s0; l1 = l1 * c1 + s1;
        m0 = nm0; m1 = nm1;
#pragma unroll
        for (int ni = 0; ni < 8; ni++) {
            oacc[ni][0] *= c0; oacc[ni][1] *= c0;
            oacc[ni][2] *= c1; oacc[ni][3] *= c1;
        }

        // ---- O += P V ----
#pragma unroll
        for (int kq = 0; kq < 8; kq++) {
#pragma unroll
            for (int ni = 0; ni < 8; ni++) {
                const float* vp = Vs + (kq * 8 + tig) * PADV + ni * 8 + gid;
                uint32_t bb[2] = { __float_as_uint(vp[0]),
                                   __float_as_uint(vp[4 * PADV]) };
                mma_tf32_16x8x8(oacc[ni], pa[kq], bb);
            }
        }
    }

    const float inv0 = 1.f / l0, inv1 = 1.f / l1;
#pragma unroll
    for (int ni = 0; ni < 8; ni++) {
        const int cc = ni * 8 + 2 * tig;
        float2 v0 = make_float2(rna_tf32(oacc[ni][0] * inv0),
                                rna_tf32(oacc[ni][1] * inv0));
        float2 v1 = make_float2(rna_tf32(oacc[ni][2] * inv1),
                                rna_tf32(oacc[ni][3] * inv1));
        *(float2*)(Og + (size_t)(wrow + gid) * INNER_ + cc) = v0;
        *(float2*)(Og + (size_t)(wrow + gid + 8) * INNER_ + cc) = v1;
    }
}

// ---------------------------------------------------------------------------
// all 4 weight transposes in one launch (z selects weight), tf32-rounded
// ---------------------------------------------------------------------------
__global__ void transpose_all(
    const float* __restrict__ Wq, const float* __restrict__ Wk,
    const float* __restrict__ Wv, const float* __restrict__ Wo,
    float* __restrict__ WqT, float* __restrict__ WkvT, float* __restrict__ WoT)
{
    __shared__ float t[32][33];
    const int z = blockIdx.z;
    const float* in; float* out; int rows, cols;
    if      (z == 0) { in = Wq; out = WqT;  rows = 1024; cols = 512; }
    else if (z == 1) { in = Wk; out = WkvT; rows = 768;  cols = 512; }
    else if (z == 2) { in = Wv; out = WkvT + (size_t)512 * 768; rows = 768; cols = 512; }
    else             { in = Wo; out = WoT;  rows = 512;  cols = 1024; }

    const int c0 = blockIdx.x * 32, r0 = blockIdx.y * 32;
    if (c0 >= cols || r0 >= rows) return;
    const int x = threadIdx.x, y = threadIdx.y;
    for (int i = y; i < 32; i += 8) {
        int r = r0 + i, c = c0 + x;
        t[i][x] = (r < rows && c < cols) ? in[(size_t)r * cols + c] : 0.f;
    }
    __syncthreads();
    for (int i = y; i < 32; i += 8) {
        int orow = c0 + i, oc = r0 + x;
        if (orow < cols && oc < rows)
            out[(size_t)orow * rows + oc] = rna_tf32(t[x][i]);
    }
}

// ---------------------------------------------------------------------------
extern "C" void kernel_launch(void* const* d_in, const int* in_sizes, int n_in,
                              void* d_out, int out_size)
{
    const float* x   = (const float*)d_in[0];
    const float* ctx = (const float*)d_in[1];
    const float* Wq  = (const float*)d_in[2];
    const float* Wk  = (const float*)d_in[3];
    const float* Wv  = (const float*)d_in[4];
    const float* Wo  = (const float*)d_in[5];
    const float* bo  = (const float*)d_in[6];
    float* out = (float*)d_out;

    float *WqT, *WkvT, *WoT, *Q, *KV, *O;
    cudaGetSymbolAddress((void**)&WqT,  g_WqT);
    cudaGetSymbolAddress((void**)&WkvT, g_WkvT);
    cudaGetSymbolAddress((void**)&WoT,  g_WoT);
    cudaGetSymbolAddress((void**)&Q,    g_Q);
    cudaGetSymbolAddress((void**)&KV,   g_KV);
    cudaGetSymbolAddress((void**)&O,    g_O);

    const int SMEM_G = 2 * (128 + 128) * 36 * 4;           // 73728 B
    const int SMEM_F = (3 * 64 * 68 + 3 * 64 * 72) * 4;    // 107520 B
    cudaFuncSetAttribute(gemm_oproj, cudaFuncAttributeMaxDynamicSharedMemorySize, SMEM_G);
    cudaFuncSetAttribute(qkv_proj,   cudaFuncAttributeMaxDynamicSharedMemorySize, SMEM_G);
    cudaFuncSetAttribute(flash_k,    cudaFuncAttributeMaxDynamicSharedMemorySize, SMEM_F);

    // 1) weight transposes (tf32-rounded), one launch
    transpose_all<<<dim3(32, 32, 4), dim3(32, 8)>>>(Wq, Wk, Wv, Wo, WqT, WkvT, WoT);

    // 2) merged Q + KV projections
    qkv_proj<<<768, 128, SMEM_G>>>(x, WqT, Q, ctx, WkvT, KV);

    // 3) fused flash attention -> O (rounded)
    flash_k<<<dim3(N_ / 128, H_, B_), 256, SMEM_F>>>(Q, KV, O);

    // 4) out = O Wo + bo  (all operands pre-rounded: no cvts)
    gemm_oproj<<<dim3(8, 128), 128, SMEM_G>>>(O, WoT, out, bo, 512, 512, 512, 1024);
}